// round 11
// baseline (speedup 1.0000x reference)
#include <cuda_runtime.h>
#include <cuda_bf16.h>
#include <cstdint>

// Problem dims (fixed)
#define T_STEPS 4
#define BATCH   16
#define NIMG    64          // T*B
#define CIN     256
#define CH      128
#define COUT    256
#define HDIM    56
#define HW      3136        // 56*56 = 49*64
#define EPSBN   1e-5f

typedef unsigned long long u64;
typedef unsigned int u32;
typedef unsigned short u16;

// ------------------------- device scratch (no malloc allowed) ---------------
#define HSPLIT ((size_t)NIMG * HW * 128)           // elements per split tensor
__device__ __nv_bfloat16 g_h1s[3 * HSPLIT];        // h1 bf16 splits, channel-last
__device__ float g_h2[(size_t)NIMG * CH * HW];     // conv2 output fp32 [img][c][hw]
// w1 bf16 splits: [split 3][kq 4][m 128][64 halves]
__device__ __nv_bfloat16 g_w1s[3 * 4 * 128 * 64];
// w2 bf16 splits: [rs 9][split 3][kh 2][m 128][64 halves]
__device__ __nv_bfloat16 g_w2a[9 * 3 * 2 * 128 * 64];
// w3 bf16 splits: [cb 2][split 3][kh 2][m 128][64 halves]
__device__ __nv_bfloat16 g_w3s[2 * 3 * 2 * 128 * 64];

// ---------------------------- mma.sync helpers ------------------------------
__device__ __forceinline__ u32 smem_u32(const void* p) {
    u32 a; asm("{ .reg .u64 t; cvta.to.shared.u64 t, %1; cvt.u32.u64 %0, t; }" : "=r"(a) : "l"(p));
    return a;
}
__device__ __forceinline__ void ldm4(u32* r, u32 addr) {
    asm volatile("ldmatrix.sync.aligned.m8n8.x4.shared.b16 {%0,%1,%2,%3}, [%4];"
        : "=r"(r[0]), "=r"(r[1]), "=r"(r[2]), "=r"(r[3]) : "r"(addr));
}
__device__ __forceinline__ void ldm2(u32* r, u32 addr) {
    asm volatile("ldmatrix.sync.aligned.m8n8.x2.shared.b16 {%0,%1}, [%2];"
        : "=r"(r[0]), "=r"(r[1]) : "r"(addr));
}
__device__ __forceinline__ void mma16816(float* d, const u32* a, const u32* b) {
    asm volatile("mma.sync.aligned.m16n8k16.row.col.f32.bf16.bf16.f32 "
        "{%0,%1,%2,%3}, {%4,%5,%6,%7}, {%8,%9}, {%0,%1,%2,%3};"
        : "+f"(d[0]), "+f"(d[1]), "+f"(d[2]), "+f"(d[3])
        : "r"(a[0]), "r"(a[1]), "r"(a[2]), "r"(a[3]), "r"(b[0]), "r"(b[1]));
}
__device__ __forceinline__ void cp16(u32 dst, const void* src, bool valid) {
    int sz = valid ? 16 : 0;
    asm volatile("cp.async.cg.shared.global [%0], [%1], 16, %2;"
                 :: "r"(dst), "l"(src), "r"(sz) : "memory");
}
__device__ __forceinline__ void cp_commit() {
    asm volatile("cp.async.commit_group;" ::: "memory");
}
__device__ __forceinline__ void cp_wait0() {
    asm volatile("cp.async.wait_group 0;" ::: "memory");
}

#define BSTR 144                      // bytes per 64-half row (128B + 16 pad)

// ---------------------------------------------------------------------------
// prep: w1 ([128][256]) -> bf16x3 splits [split 3][kq 4][m 128][64]
// ---------------------------------------------------------------------------
__global__ void prep_w1s_kernel(const float* __restrict__ w1) {
    int idx = blockIdx.x * blockDim.x + threadIdx.x;
    if (idx >= 128 * 256) return;
    int k = idx & 255;
    int m = idx >> 8;
    float w = w1[(size_t)m * 256 + k];
    __nv_bfloat16 b0 = __float2bfloat16_rn(w);
    float r1 = w - __bfloat162float(b0);
    __nv_bfloat16 b1 = __float2bfloat16_rn(r1);
    float r2 = r1 - __bfloat162float(b1);
    __nv_bfloat16 b2 = __float2bfloat16_rn(r2);
    int kq = k >> 6, ko = k & 63;
    size_t base = (((size_t)kq * 128) + m) * 64 + ko;
    size_t sstep = (size_t)4 * 128 * 64;
    g_w1s[base]             = b0;
    g_w1s[base + sstep]     = b1;
    g_w1s[base + 2 * sstep] = b2;
}

// ---------------------------------------------------------------------------
// prep: w2 (OIHW [128][128][3][3]) -> bf16x3 splits [rs][split][kh][m][64]
// ---------------------------------------------------------------------------
__global__ void prep_w2a_kernel(const float* __restrict__ w2) {
    int idx = blockIdx.x * blockDim.x + threadIdx.x;
    if (idx >= 9 * 128 * 128) return;
    int k = idx & 127;
    int m = (idx >> 7) & 127;
    int rs = idx >> 14;
    float w = w2[((size_t)(m * 128 + k)) * 9 + rs];
    __nv_bfloat16 b0 = __float2bfloat16_rn(w);
    float r1 = w - __bfloat162float(b0);
    __nv_bfloat16 b1 = __float2bfloat16_rn(r1);
    float r2 = r1 - __bfloat162float(b1);
    __nv_bfloat16 b2 = __float2bfloat16_rn(r2);
    int kh = k >> 6, ko = k & 63;
    size_t base = ((((size_t)rs * 3) * 2 + kh) * 128 + m) * 64 + ko;
    size_t sstep = (size_t)2 * 128 * 64;   // stride between splits
    g_w2a[base]             = b0;
    g_w2a[base + sstep]     = b1;
    g_w2a[base + 2 * sstep] = b2;
}

// ---------------------------------------------------------------------------
// prep: w3 ([256][128]) -> bf16x3 splits [cb 2][split 3][kh 2][m 128][64]
// ---------------------------------------------------------------------------
__global__ void prep_w3s_kernel(const float* __restrict__ w3) {
    int idx = blockIdx.x * blockDim.x + threadIdx.x;
    if (idx >= 256 * 128) return;
    int k = idx & 127;
    int mg = idx >> 7;            // 0..255
    int cb = mg >> 7, m = mg & 127;
    float w = w3[(size_t)mg * 128 + k];
    __nv_bfloat16 b0 = __float2bfloat16_rn(w);
    float r1 = w - __bfloat162float(b0);
    __nv_bfloat16 b1 = __float2bfloat16_rn(r1);
    float r2 = r1 - __bfloat162float(b1);
    __nv_bfloat16 b2 = __float2bfloat16_rn(r2);
    int kh = k >> 6, ko = k & 63;
    size_t sstep = (size_t)2 * 128 * 64;
    size_t base = ((((size_t)cb * 3) * 2 + kh) * 128 + m) * 64 + ko;
    g_w3s[base]             = b0;
    g_w3s[base + sstep]     = b1;
    g_w3s[base + 2 * sstep] = b2;
}

// ---------------------------------------------------------------------------
// conv1: 1x1 256->128 + BN via mma.sync bf16x3 6-term. (round 10, passing)
// ---------------------------------------------------------------------------
#define C1_A_SPLIT 18432     // 128 m * 144
#define C1_B_OFF   55296     // 3 * C1_A_SPLIT
#define C1_B_SPLIT 9216      // 64 px * 144
#define C1_F_OFF   82944     // fp32 staging 64k x 64px = 16KB (xor-swizzled)
#define SMEM_CONV1 (C1_F_OFF + 16384)   // 99328

__global__ __launch_bounds__(256) void conv1_hmma_kernel(
    const float* __restrict__ X,   // x [NIMG][256][HW]
    const float* __restrict__ gg, const float* __restrict__ bb,
    const float* __restrict__ mm, const float* __restrict__ vv)
{
    extern __shared__ char smem[];
    const u32 sb = smem_u32(smem);
    const int tid = threadIdx.x;
    const int wid = tid >> 5;
    const int lane = tid & 31;
    const int hw0 = blockIdx.x * 64;
    const int img = blockIdx.y;
    const int m0 = (wid & 3) * 32;
    const int n0 = (wid >> 2) * 32;

    const u32 aLane = (u32)(((lane & 7) + (lane & 8)) * BSTR + ((lane >> 4) & 1) * 16);
    const u32 bLane4 = (u32)((lane & 7) * BSTR + ((lane >> 3) & 1) * 16
                             + ((lane >> 4) & 1) * 8 * BSTR);
    const int g = lane >> 2;
    const int t2 = lane & 3;

    float tot[2][4][4];
    float work[2][4][4];
#pragma unroll
    for (int a = 0; a < 2; a++)
#pragma unroll
        for (int n = 0; n < 4; n++)
#pragma unroll
            for (int d = 0; d < 4; d++) { tot[a][n][d] = 0.f; work[a][n][d] = 0.f; }

    // combo order per chunk: main first (flushed), corrections chained
    const int AI[6] = {0, 0, 1, 1, 0, 2};
    const int BJ[6] = {0, 1, 0, 1, 2, 0};

#pragma unroll 1
    for (int kc = 0; kc < 4; kc++) {
        __syncthreads();   // protect smem from previous chunk's reads
        // ---- load x fp32 chunk [64 k][64 px] into xor-swizzled staging ----
#pragma unroll
        for (int q = 0; q < 4; q++) {
            int f = tid + q * 256;       // 0..1023 float4 units
            int k = f >> 4, c4 = f & 15;
            float4 v4 = *(const float4*)&X[((size_t)img * CIN + kc * 64 + k) * HW + hw0 + c4 * 4];
            *(float4*)(smem + C1_F_OFF + k * 256 + ((c4 ^ (k & 15)) * 16)) = v4;
        }
        // ---- stage A chunk: 3 splits x 128 m x 64 k ----
#pragma unroll
        for (int q = 0; q < 12; q++) {
            int f = tid + q * 256;       // 0..3071
            int qq = f & 7;
            int row = f >> 3;            // 0..383
            int m = row & 127;
            int split = row >> 7;
            u32 dst = sb + split * C1_A_SPLIT + m * BSTR + qq * 16;
            const char* src = (const char*)g_w1s +
                ((((size_t)split * 4 + kc) * 128 + m) * 128 + qq * 16);
            cp16(dst, src, true);
        }
        cp_commit();
        __syncthreads();
        // ---- convert x chunk to bf16x3 [split][px][64k] ----
        {
            int px = tid & 63, kg = tid >> 6;    // kg 0..3, 16 k each
            u32 pr0 = 0, pr1 = 0, pr2 = 0;
#pragma unroll
            for (int i = 0; i < 16; i++) {
                int k = kg * 16 + i;
                float h = *(const float*)(smem + C1_F_OFF + k * 256 +
                                          (((px >> 2) ^ (k & 15)) * 16) + (px & 3) * 4);
                __nv_bfloat16 c0 = __float2bfloat16_rn(h);
                float r1 = h - __bfloat162float(c0);
                __nv_bfloat16 c1 = __float2bfloat16_rn(r1);
                float r2 = r1 - __bfloat162float(c1);
                __nv_bfloat16 c2 = __float2bfloat16_rn(r2);
                if ((i & 1) == 0) {
                    pr0 = *(u16*)&c0; pr1 = *(u16*)&c1; pr2 = *(u16*)&c2;
                } else {
                    int ko = k - 1;
                    u32 base = C1_B_OFF + px * BSTR + ko * 2;
                    *(u32*)(smem + base)                  = pr0 | ((u32)*(u16*)&c0 << 16);
                    *(u32*)(smem + base + C1_B_SPLIT)     = pr1 | ((u32)*(u16*)&c1 << 16);
                    *(u32*)(smem + base + 2 * C1_B_SPLIT) = pr2 | ((u32)*(u16*)&c2 << 16);
                }
            }
        }
        cp_wait0();
        __syncthreads();

        // ---- MMA: 6 combos x 4 ksteps ----
#pragma unroll 1
        for (int c = 0; c < 6; c++) {
            const int ai = AI[c], bj = BJ[c];
#pragma unroll
            for (int ks = 0; ks < 4; ks++) {
                u32 afr[2][4];
                u32 ab = sb + ai * C1_A_SPLIT + (u32)(m0 * BSTR) + aLane + ks * 32;
                ldm4(afr[0], ab);
                ldm4(afr[1], ab + 16 * BSTR);
                const u32 bbase = sb + C1_B_OFF + bj * C1_B_SPLIT + (u32)(ks * 32);
#pragma unroll
                for (int np = 0; np < 2; np++) {
                    u32 b4[4];
                    ldm4(b4, bbase + (u32)((n0 + np * 16) * BSTR) + bLane4);
                    mma16816(work[0][2 * np],     afr[0], b4);
                    mma16816(work[1][2 * np],     afr[1], b4);
                    mma16816(work[0][2 * np + 1], afr[0], b4 + 2);
                    mma16816(work[1][2 * np + 1], afr[1], b4 + 2);
                }
            }
            if (c == 0) {   // flush main term per chunk
#pragma unroll
                for (int a = 0; a < 2; a++)
#pragma unroll
                    for (int n = 0; n < 4; n++)
#pragma unroll
                        for (int d = 0; d < 4; d++) {
                            tot[a][n][d] += work[a][n][d];
                            work[a][n][d] = 0.f;
                        }
            }
        }
    }
    // final correction flush
#pragma unroll
    for (int a = 0; a < 2; a++)
#pragma unroll
        for (int n = 0; n < 4; n++)
#pragma unroll
            for (int d = 0; d < 4; d++) tot[a][n][d] += work[a][n][d];

    // ---- epilogue: BN, then bf16x3 split via smem transpose ----
    float scv[2][2], biv[2][2];
#pragma unroll
    for (int mt = 0; mt < 2; mt++)
#pragma unroll
        for (int h = 0; h < 2; h++) {
            int c = m0 + mt * 16 + g + h * 8;
            float sc = gg[c] / sqrtf(vv[c] + EPSBN);
            scv[mt][h] = sc;
            biv[mt][h] = bb[c] - mm[c] * sc;
        }
    // residual state in tot
#pragma unroll
    for (int mt = 0; mt < 2; mt++)
#pragma unroll
        for (int nt = 0; nt < 4; nt++)
#pragma unroll
            for (int d = 0; d < 4; d++)
                tot[mt][nt][d] = tot[mt][nt][d] * scv[mt][d >> 1] + biv[mt][d >> 1];

#pragma unroll 1
    for (int j = 0; j < 3; j++) {
        __syncthreads();
        // write split-j halves into smem [px 64][c 128]
#pragma unroll
        for (int mt = 0; mt < 2; mt++)
#pragma unroll
            for (int nt = 0; nt < 4; nt++)
#pragma unroll
                for (int d = 0; d < 4; d++) {
                    float r = tot[mt][nt][d];
                    __nv_bfloat16 bj = __float2bfloat16_rn(r);
                    tot[mt][nt][d] = r - __bfloat162float(bj);
                    int pxl = n0 + nt * 8 + 2 * t2 + (d & 1);
                    int c = m0 + mt * 16 + g + (d >> 1) * 8;
                    *(u16*)(smem + C1_F_OFF + (pxl * 128 + c) * 2) = *(u16*)&bj;
                }
        __syncthreads();
        // coalesced copy out: 16 uint4 per px row (128 c * 2B = 256B)
#pragma unroll
        for (int q = 0; q < 4; q++) {
            int u = tid + q * 256;       // 0..1023 uint4
            int px = u >> 4, c8 = (u & 15) * 8;
            *(uint4*)&g_h1s[(size_t)j * HSPLIT +
                            ((size_t)img * HW + hw0 + px) * 128 + c8] =
                *(uint4*)(smem + C1_F_OFF + u * 16);
        }
    }
}

// ---------------------------------------------------------------------------
// conv2: 3x3 128->128 + BN via mma.sync bf16x3 (Ootomo discipline).
// RESTRUCTURED for 2 CTAs/SM: block = (img, 1 output row y). 8 warps = 8
// M-slices of 16. B = 3 splits x 3 input rows x 58 px (75.2KB) + A dbl-buf
// (36.9KB) = 112KB smem. Same 36-iteration schedule, bit-identical numerics.
// ---------------------------------------------------------------------------
#define SB_ROW (58 * BSTR)            // 8352
#define SB_SPLIT3 (3 * SB_ROW)        // 25056
#define A_OFF (3 * SB_SPLIT3)         // 75168
#define A_BUFSZ (128 * BSTR)          // 18432
#define SMEM_CONV2 (A_OFF + 2 * A_BUFSZ)   // 112032

__device__ __forceinline__ void sched36(int it, int& split, int& tap, int& bjs, int& nbj) {
    if (it < 9)       { split = 0; tap = it;      bjs = 0; nbj = 1; }   // main
    else if (it < 18) { split = 0; tap = it - 9;  bjs = 1; nbj = 2; }   // a0b1, a0b2
    else if (it < 27) { split = 1; tap = it - 18; bjs = 0; nbj = 2; }   // a1b0, a1b1
    else              { split = 2; tap = it - 27; bjs = 0; nbj = 1; }   // a2b0
}

__global__ __launch_bounds__(256, 2) void conv2_hmma_kernel(
    const float* __restrict__ gg, const float* __restrict__ bb,
    const float* __restrict__ mm, const float* __restrict__ vv)
{
    extern __shared__ char smem[];
    const u32 sb = smem_u32(smem);
    const int tid = threadIdx.x;
    const int wid = tid >> 5;
    const int lane = tid & 31;
    const int img = blockIdx.y;
    const int y = blockIdx.x;         // single output row
    const int m0 = wid * 16;          // warp M slice (16 rows)

    float totals[7][4];
    float work[7][4];
#pragma unroll
    for (int n = 0; n < 7; n++)
#pragma unroll
        for (int d = 0; d < 4; d++) { totals[n][d] = 0.f; work[n][d] = 0.f; }

    const u32 aLane = (u32)(((lane & 7) + (lane & 8)) * BSTR + ((lane >> 4) & 1) * 16);
    const u32 bLane2 = (u32)((lane & 7) * BSTR + ((lane >> 3) & 1) * 16);
    const u32 bLane4 = bLane2 + (u32)(((lane >> 4) & 1) * (8 * BSTR));

    for (int kh = 0; kh < 2; kh++) {
        // ---- stage B: 3 splits x 3 input rows x 58 px x 64 halves ----
        for (int f = tid; f < 3 * 3 * 58 * 8; f += 256) {
            int q = f & 7;
            int p = f >> 3;           // 0..521
            int px = p % 58;
            int t = p / 58;           // 0..8
            int ri = t % 3;
            int split = t / 3;
            int yi = y - 1 + ri;
            int x = px - 1;
            bool valid = ((unsigned)yi < (unsigned)HDIM) && ((unsigned)x < (unsigned)HDIM);
            u32 dst = sb + split * SB_SPLIT3 + ri * SB_ROW + px * BSTR + q * 16;
            const char* src = (const char*)g_h1s +
                (((size_t)split * HSPLIT +
                  (((size_t)img * HW + (valid ? (yi * HDIM + x) : 0)) * 128 + kh * 64 + q * 8)) << 1);
            cp16(dst, src, valid);
        }
        cp_commit();
        {   // A tile for it=0 (tap0, split0)
            const char* tbase = (const char*)g_w2a + ((size_t)(0 * 3 + 0) * 2 + kh) * 8192 * 2;
#pragma unroll
            for (int q = 0; q < 4; q++) {
                int f = tid + q * 256;
                cp16(sb + A_OFF + (f >> 3) * BSTR + (f & 7) * 16, tbase + (size_t)f * 16, true);
            }
            cp_commit();
        }
        cp_wait0();
        __syncthreads();

#pragma unroll 1
        for (int it = 0; it < 36; it++) {
            if (it < 35) {
                int nsplit, ntap, nbjs, nnbj;
                sched36(it + 1, nsplit, ntap, nbjs, nnbj);
                const char* tbase = (const char*)g_w2a +
                    ((size_t)((ntap * 3 + nsplit) * 2 + kh) * 8192) * 2;
                u32 abase = sb + A_OFF + ((it + 1) & 1) * A_BUFSZ;
#pragma unroll
                for (int q = 0; q < 4; q++) {
                    int f = tid + q * 256;
                    cp16(abase + (f >> 3) * BSTR + (f & 7) * 16, tbase + (size_t)f * 16, true);
                }
                cp_commit();
            }
            int split, tap, bjs, nbj;
            sched36(it, split, tap, bjs, nbj);
            const int r = tap / 3;
            const int s = tap - r * 3;
            const u32 ab = sb + A_OFF + (it & 1) * A_BUFSZ;

#pragma unroll
            for (int ks = 0; ks < 4; ks++) {
                u32 afr[4];
                ldm4(afr, ab + (u32)(m0 * BSTR) + aLane + ks * 32);
#pragma unroll 1
                for (int j = 0; j < nbj; j++) {
                    const u32 bbase = sb + (bjs + j) * SB_SPLIT3 + r * SB_ROW
                                      + (u32)(ks * 32);
#pragma unroll
                    for (int np = 0; np < 3; np++) {   // x-group pairs (0,1)(2,3)(4,5)
                        u32 b4[4];
                        ldm4(b4, bbase + (np * 16 + s) * BSTR + bLane4);
                        mma16816(work[2 * np],     afr, b4);
                        mma16816(work[2 * np + 1], afr, b4 + 2);
                    }
                    u32 b2[2];
                    ldm2(b2, bbase + (48 + s) * BSTR + bLane2);
                    mma16816(work[6], afr, b2);
                }
            }
            cp_wait0();
            __syncthreads();
            if (it < 9 || it == 35) {
#pragma unroll
                for (int n = 0; n < 7; n++)
#pragma unroll
                    for (int d = 0; d < 4; d++) {
                        totals[n][d] += work[n][d];
                        work[n][d] = 0.f;
                    }
            }
        }
    }

    // ---- epilogue: BN + store fp32 to g_h2 [img][c][hw] ----
    const int g = lane >> 2;
    const int t2 = lane & 3;
    float scv[2], biv[2];
#pragma unroll
    for (int h = 0; h < 2; h++) {
        int c = m0 + g + h * 8;
        float sc = gg[c] / sqrtf(vv[c] + EPSBN);
        scv[h] = sc;
        biv[h] = bb[c] - mm[c] * sc;
    }
    float* outimg = g_h2 + (size_t)img * CH * HW;
#pragma unroll
    for (int nt = 0; nt < 7; nt++) {
        int xo = nt * 8 + 2 * t2;
        int clo = m0 + g;
        float2 vlo = make_float2(totals[nt][0] * scv[0] + biv[0],
                                 totals[nt][1] * scv[0] + biv[0]);
        float2 vhi = make_float2(totals[nt][2] * scv[1] + biv[1],
                                 totals[nt][3] * scv[1] + biv[1]);
        *(float2*)&outimg[(size_t)clo * HW + y * HDIM + xo] = vlo;
        *(float2*)&outimg[(size_t)(clo + 8) * HW + y * HDIM + xo] = vhi;
    }
}

// ---------------------------------------------------------------------------
// conv3 + BN + LIF fused, bf16x3 6-term (round 6, proven).
// grid (49 hw-tiles of 64 px, 16 batch, 2 cb). 256 thr = 8 warps (4M x 2N).
// ---------------------------------------------------------------------------
#define C3_A_SPLIT 36864      // 2 kh * 128 m * 144
#define C3_A_KH    18432
#define C3_B_OFF   110592     // 3 * C3_A_SPLIT
#define C3_B_SPLIT 18432      // 2 kh * 64 px * 144
#define C3_B_KH    9216
#define C3_F_OFF   165888     // fp32 staging, 32KB, xor-swizzled float4s
#define SMEM_CONV3 (C3_F_OFF + 32768)   // 198656

__global__ __launch_bounds__(256) void conv3_lif_kernel(
    const float* __restrict__ gg, const float* __restrict__ bb,
    const float* __restrict__ mm, const float* __restrict__ vv,
    float* __restrict__ out)
{
    extern __shared__ char smem[];
    const u32 sb = smem_u32(smem);
    const int tid = threadIdx.x;
    const int wid = tid >> 5;
    const int lane = tid & 31;
    const int hw0 = blockIdx.x * 64;
    const int bidx = blockIdx.y;
    const int cb = blockIdx.z;
    const int m0 = (wid & 3) * 32;
    const int n0 = (wid >> 2) * 32;

    // ---- stage A once: 3 splits x 2 kh x 128 m x 128B (144B stride) ----
    for (int f = tid; f < 6144; f += 256) {
        int q = f & 7;
        int row = f >> 3;              // 0..767
        int m = row & 127;
        int kh = (row >> 7) & 1;
        int split = row >> 8;
        u32 dst = sb + split * C3_A_SPLIT + kh * C3_A_KH + m * BSTR + q * 16;
        const char* src = (const char*)g_w3s +
            ((((size_t)(cb * 3 + split) * 2 + kh) * 128 + m) * 128 + q * 16);
        cp16(dst, src, true);
    }
    cp_commit();

    const u32 aLane = (u32)(((lane & 7) + (lane & 8)) * BSTR + ((lane >> 4) & 1) * 16);
    const u32 bLane4 = (u32)((lane & 7) * BSTR + ((lane >> 3) & 1) * 16
                             + ((lane >> 4) & 1) * 8 * BSTR);
    const int g = lane >> 2;
    const int t2 = lane & 3;

    float scv[2][2], biv[2][2];
#pragma unroll
    for (int mt = 0; mt < 2; mt++)
#pragma unroll
        for (int h = 0; h < 2; h++) {
            int c = cb * 128 + m0 + mt * 16 + g + h * 8;
            float sc = gg[c] / sqrtf(vv[c] + EPSBN);
            scv[mt][h] = sc;
            biv[mt][h] = bb[c] - mm[c] * sc;
        }

    float vst[2][4][4];
#pragma unroll
    for (int a = 0; a < 2; a++)
#pragma unroll
        for (int n = 0; n < 4; n++)
#pragma unroll
            for (int d = 0; d < 4; d++) vst[a][n][d] = 0.f;

    // combo order: corrections first (acc small -> RZ harmless), main last
    const int AI[6] = {0, 0, 1, 1, 2, 0};
    const int BJ[6] = {1, 2, 0, 1, 0, 0};

#pragma unroll 1
    for (int t = 0; t < T_STEPS; t++) {
        const int img = t * BATCH + bidx;
        __syncthreads();   // protect B smem from previous iteration's reads

        // ---- load h2 fp32 tile [k=128][px=64] into xor-swizzled staging ----
#pragma unroll
        for (int q = 0; q < 8; q++) {
            int f = tid + q * 256;
            int k = f >> 4, c4 = f & 15;
            float4 v4 = *(const float4*)&g_h2[((size_t)img * CH + k) * HW + hw0 + c4 * 4];
            *(float4*)(smem + C3_F_OFF + k * 256 + ((c4 ^ (k & 15)) * 16)) = v4;
        }
        __syncthreads();

        // ---- convert to bf16x3 [split][kh][px][64k] ----
        {
            int px = tid & 63, kg = tid >> 6;    // kg 0..3
            u32 pr0 = 0, pr1 = 0, pr2 = 0;
#pragma unroll
            for (int i = 0; i < 32; i++) {
                int k = kg * 32 + i;
                float h = *(const float*)(smem + C3_F_OFF + k * 256 +
                                          (((px >> 2) ^ (k & 15)) * 16) + (px & 3) * 4);
                __nv_bfloat16 c0 = __float2bfloat16_rn(h);
                float r1 = h - __bfloat162float(c0);
                __nv_bfloat16 c1 = __float2bfloat16_rn(r1);
                float r2 = r1 - __bfloat162float(c1);
                __nv_bfloat16 c2 = __float2bfloat16_rn(r2);
                if ((i & 1) == 0) {
                    pr0 = *(u16*)&c0; pr1 = *(u16*)&c1; pr2 = *(u16*)&c2;
                } else {
                    int kh = k >> 6, ko = (k & 63) - 1;
                    u32 base = C3_B_OFF + kh * C3_B_KH + px * BSTR + ko * 2;
                    *(u32*)(smem + base)                  = pr0 | ((u32)*(u16*)&c0 << 16);
                    *(u32*)(smem + base + C3_B_SPLIT)     = pr1 | ((u32)*(u16*)&c1 << 16);
                    *(u32*)(smem + base + 2 * C3_B_SPLIT) = pr2 | ((u32)*(u16*)&c2 << 16);
                }
            }
        }
        if (t == 0) cp_wait0();    // A tiles arrived
        __syncthreads();

        float tot[2][4][4];
#pragma unroll
        for (int a = 0; a < 2; a++)
#pragma unroll
            for (int n = 0; n < 4; n++)
#pragma unroll
                for (int d = 0; d < 4; d++) tot[a][n][d] = 0.f;

        // corrections (combos 0-4) chained, flushed once; then main chained
        float acc[2][4][4];
#pragma unroll
        for (int a = 0; a < 2; a++)
#pragma unroll
            for (int n = 0; n < 4; n++)
#pragma unroll
                for (int d = 0; d < 4; d++) acc[a][n][d] = 0.f;

#pragma unroll 1
        for (int c = 0; c < 6; c++) {
            const int ai = AI[c], bj = BJ[c];
#pragma unroll
            for (int kh = 0; kh < 2; kh++) {
#pragma unroll
                for (int ks = 0; ks < 4; ks++) {
                    u32 afr[2][4];
                    u32 ab = sb + ai * C3_A_SPLIT + kh * C3_A_KH + (u32)(m0 * BSTR)
                             + aLane + ks * 32;
                    ldm4(afr[0], ab);
                    ldm4(afr[1], ab + 16 * BSTR);
                    const u32 bbase = sb + C3_B_OFF + bj * C3_B_SPLIT + kh * C3_B_KH
                                      + (u32)(ks * 32);
#pragma unroll
                    for (int np = 0; np < 2; np++) {
                        u32 b4[4];
                        ldm4(b4, bbase + (u32)((n0 + np * 16) * BSTR) + bLane4);
                        mma16816(acc[0][2 * np],     afr[0], b4);
                        mma16816(acc[1][2 * np],     afr[1], b4);
                        mma16816(acc[0][2 * np + 1], afr[0], b4 + 2);
                        mma16816(acc[1][2 * np + 1], afr[1], b4 + 2);
                    }
                }
            }
            if (c == 4) {   // flush corrections before the main term
#pragma unroll
                for (int a = 0; a < 2; a++)
#pragma unroll
                    for (int n = 0; n < 4; n++)
#pragma unroll
                        for (int d = 0; d < 4; d++) {
                            tot[a][n][d] += acc[a][n][d];
                            acc[a][n][d] = 0.f;
                        }
            }
        }
#pragma unroll
        for (int a = 0; a < 2; a++)
#pragma unroll
            for (int n = 0; n < 4; n++)
#pragma unroll
                for (int d = 0; d < 4; d++) tot[a][n][d] += acc[a][n][d];

        // ---- epilogue: BN + LIF + store spikes ----
#pragma unroll
        for (int nt = 0; nt < 4; nt++) {
            int n = n0 + nt * 8 + 2 * t2;
#pragma unroll
            for (int mt = 0; mt < 2; mt++) {
                int clo = cb * 128 + m0 + mt * 16 + g;
                float s[4];
#pragma unroll
                for (int d = 0; d < 4; d++) {
                    int h = d >> 1;
                    float h3 = tot[mt][nt][d] * scv[mt][h] + biv[mt][h];
                    float v = vst[mt][nt][d];
                    v = v + (h3 - v) * 0.5f;
                    float sp = (v >= 1.0f) ? 1.0f : 0.0f;
                    s[d] = sp;
                    vst[mt][nt][d] = v * (1.0f - sp);
                }
                *(float2*)&out[((size_t)img * COUT + clo) * HW + hw0 + n] =
                    make_float2(s[0], s[1]);
                *(float2*)&out[((size_t)img * COUT + clo + 8) * HW + hw0 + n] =
                    make_float2(s[2], s[3]);
            }
        }
    }
}

// ---------------------------------------------------------------------------
extern "C" void kernel_launch(void* const* d_in, const int* in_sizes, int n_in,
                              void* d_out, int out_size)
{
    const float* x  = (const float*)d_in[0];
    const float* w1 = (const float*)d_in[1];
    const float* g1 = (const float*)d_in[2];
    const float* b1 = (const float*)d_in[3];
    const float* m1 = (const float*)d_in[4];
    const float* v1 = (const float*)d_in[5];
    const float* w2 = (const float*)d_in[6];
    const float* g2 = (const float*)d_in[7];
    const float* b2 = (const float*)d_in[8];
    const float* m2 = (const float*)d_in[9];
    const float* v2 = (const float*)d_in[10];
    const float* w3 = (const float*)d_in[11];
    const float* g3 = (const float*)d_in[12];
    const float* b3 = (const float*)d_in[13];
    const float* m3 = (const float*)d_in[14];
    const float* v3 = (const float*)d_in[15];
    float* out = (float*)d_out;

    cudaFuncSetAttribute(conv1_hmma_kernel,
                         cudaFuncAttributeMaxDynamicSharedMemorySize, SMEM_CONV1);
    cudaFuncSetAttribute(conv2_hmma_kernel,
                         cudaFuncAttributeMaxDynamicSharedMemorySize, SMEM_CONV2);
    cudaFuncSetAttribute(conv3_lif_kernel,
                         cudaFuncAttributeMaxDynamicSharedMemorySize, SMEM_CONV3);

    // weight splits
    prep_w1s_kernel<<<(128 * 256 + 255) / 256, 256>>>(w1);
    prep_w2a_kernel<<<(9 * 128 * 128 + 255) / 256, 256>>>(w2);
    prep_w3s_kernel<<<(256 * 128 + 255) / 256, 256>>>(w3);

    // conv1: 1x1 256->128 + BN1 via HMMA -> bf16x3 channel-last splits
    conv1_hmma_kernel<<<dim3(49, NIMG), 256, SMEM_CONV1>>>(x, g1, b1, m1, v1);

    // conv2: 3x3 128->128 + BN2 via mma.sync (1-row blocks, 2 CTAs/SM) -> g_h2
    conv2_hmma_kernel<<<dim3(HDIM, NIMG), 256, SMEM_CONV2>>>(g2, b2, m2, v2);

    // conv3 + BN3 + LIF fused -> d_out spikes
    conv3_lif_kernel<<<dim3(49, BATCH, 2), 256, SMEM_CONV3>>>(g3, b3, m3, v3, out);
}

// round 12
// speedup vs baseline: 1.0360x; 1.0360x over previous
#include <cuda_runtime.h>
#include <cuda_bf16.h>
#include <cstdint>

// Problem dims (fixed)
#define T_STEPS 4
#define BATCH   16
#define NIMG    64          // T*B
#define CIN     256
#define CH      128
#define COUT    256
#define HDIM    56
#define HW      3136        // 56*56 = 49*64
#define EPSBN   1e-5f

typedef unsigned long long u64;
typedef unsigned int u32;
typedef unsigned short u16;

// ------------------------- device scratch (no malloc allowed) ---------------
#define HSPLIT ((size_t)NIMG * HW * 128)           // elements per split tensor
__device__ __nv_bfloat16 g_h1s[3 * HSPLIT];        // h1 bf16 splits, channel-last
__device__ float g_h2[(size_t)NIMG * CH * HW];     // conv2 output fp32 [img][c][hw]
// w1 bf16 splits: [split 3][kq 4][m 128][64 halves]
__device__ __nv_bfloat16 g_w1s[3 * 4 * 128 * 64];
// w2 bf16 splits: [rs 9][split 3][kh 2][m 128][64 halves]
__device__ __nv_bfloat16 g_w2a[9 * 3 * 2 * 128 * 64];
// w3 bf16 splits: [cb 2][split 3][kh 2][m 128][64 halves]
__device__ __nv_bfloat16 g_w3s[2 * 3 * 2 * 128 * 64];

// ---------------------------- mma.sync helpers ------------------------------
__device__ __forceinline__ u32 smem_u32(const void* p) {
    u32 a; asm("{ .reg .u64 t; cvta.to.shared.u64 t, %1; cvt.u32.u64 %0, t; }" : "=r"(a) : "l"(p));
    return a;
}
__device__ __forceinline__ void ldm4(u32* r, u32 addr) {
    asm volatile("ldmatrix.sync.aligned.m8n8.x4.shared.b16 {%0,%1,%2,%3}, [%4];"
        : "=r"(r[0]), "=r"(r[1]), "=r"(r[2]), "=r"(r[3]) : "r"(addr));
}
__device__ __forceinline__ void ldm2(u32* r, u32 addr) {
    asm volatile("ldmatrix.sync.aligned.m8n8.x2.shared.b16 {%0,%1}, [%2];"
        : "=r"(r[0]), "=r"(r[1]) : "r"(addr));
}
__device__ __forceinline__ void mma16816(float* d, const u32* a, const u32* b) {
    asm volatile("mma.sync.aligned.m16n8k16.row.col.f32.bf16.bf16.f32 "
        "{%0,%1,%2,%3}, {%4,%5,%6,%7}, {%8,%9}, {%0,%1,%2,%3};"
        : "+f"(d[0]), "+f"(d[1]), "+f"(d[2]), "+f"(d[3])
        : "r"(a[0]), "r"(a[1]), "r"(a[2]), "r"(a[3]), "r"(b[0]), "r"(b[1]));
}
__device__ __forceinline__ void cp16(u32 dst, const void* src, bool valid) {
    int sz = valid ? 16 : 0;
    asm volatile("cp.async.cg.shared.global [%0], [%1], 16, %2;"
                 :: "r"(dst), "l"(src), "r"(sz) : "memory");
}
__device__ __forceinline__ void cp_commit() {
    asm volatile("cp.async.commit_group;" ::: "memory");
}
__device__ __forceinline__ void cp_wait0() {
    asm volatile("cp.async.wait_group 0;" ::: "memory");
}

#define BSTR 144                      // bytes per 64-half row (128B + 16 pad)

// ---------------------------------------------------------------------------
// prep: w1 ([128][256]) -> bf16x3 splits [split 3][kq 4][m 128][64]
// ---------------------------------------------------------------------------
__global__ void prep_w1s_kernel(const float* __restrict__ w1) {
    int idx = blockIdx.x * blockDim.x + threadIdx.x;
    if (idx >= 128 * 256) return;
    int k = idx & 255;
    int m = idx >> 8;
    float w = w1[(size_t)m * 256 + k];
    __nv_bfloat16 b0 = __float2bfloat16_rn(w);
    float r1 = w - __bfloat162float(b0);
    __nv_bfloat16 b1 = __float2bfloat16_rn(r1);
    float r2 = r1 - __bfloat162float(b1);
    __nv_bfloat16 b2 = __float2bfloat16_rn(r2);
    int kq = k >> 6, ko = k & 63;
    size_t base = (((size_t)kq * 128) + m) * 64 + ko;
    size_t sstep = (size_t)4 * 128 * 64;
    g_w1s[base]             = b0;
    g_w1s[base + sstep]     = b1;
    g_w1s[base + 2 * sstep] = b2;
}

// ---------------------------------------------------------------------------
// prep: w2 (OIHW [128][128][3][3]) -> bf16x3 splits [rs][split][kh][m][64]
// ---------------------------------------------------------------------------
__global__ void prep_w2a_kernel(const float* __restrict__ w2) {
    int idx = blockIdx.x * blockDim.x + threadIdx.x;
    if (idx >= 9 * 128 * 128) return;
    int k = idx & 127;
    int m = (idx >> 7) & 127;
    int rs = idx >> 14;
    float w = w2[((size_t)(m * 128 + k)) * 9 + rs];
    __nv_bfloat16 b0 = __float2bfloat16_rn(w);
    float r1 = w - __bfloat162float(b0);
    __nv_bfloat16 b1 = __float2bfloat16_rn(r1);
    float r2 = r1 - __bfloat162float(b1);
    __nv_bfloat16 b2 = __float2bfloat16_rn(r2);
    int kh = k >> 6, ko = k & 63;
    size_t base = ((((size_t)rs * 3) * 2 + kh) * 128 + m) * 64 + ko;
    size_t sstep = (size_t)2 * 128 * 64;   // stride between splits
    g_w2a[base]             = b0;
    g_w2a[base + sstep]     = b1;
    g_w2a[base + 2 * sstep] = b2;
}

// ---------------------------------------------------------------------------
// prep: w3 ([256][128]) -> bf16x3 splits [cb 2][split 3][kh 2][m 128][64]
// ---------------------------------------------------------------------------
__global__ void prep_w3s_kernel(const float* __restrict__ w3) {
    int idx = blockIdx.x * blockDim.x + threadIdx.x;
    if (idx >= 256 * 128) return;
    int k = idx & 127;
    int mg = idx >> 7;            // 0..255
    int cb = mg >> 7, m = mg & 127;
    float w = w3[(size_t)mg * 128 + k];
    __nv_bfloat16 b0 = __float2bfloat16_rn(w);
    float r1 = w - __bfloat162float(b0);
    __nv_bfloat16 b1 = __float2bfloat16_rn(r1);
    float r2 = r1 - __bfloat162float(b1);
    __nv_bfloat16 b2 = __float2bfloat16_rn(r2);
    int kh = k >> 6, ko = k & 63;
    size_t sstep = (size_t)2 * 128 * 64;
    size_t base = ((((size_t)cb * 3) * 2 + kh) * 128 + m) * 64 + ko;
    g_w3s[base]             = b0;
    g_w3s[base + sstep]     = b1;
    g_w3s[base + 2 * sstep] = b2;
}

// ---------------------------------------------------------------------------
// conv1: 1x1 256->128 + BN via mma.sync bf16x3 6-term. (round 10, 318us, proven)
// ---------------------------------------------------------------------------
#define C1_A_SPLIT 18432     // 128 m * 144
#define C1_B_OFF   55296     // 3 * C1_A_SPLIT
#define C1_B_SPLIT 9216      // 64 px * 144
#define C1_F_OFF   82944     // fp32 staging 64k x 64px = 16KB (xor-swizzled)
#define SMEM_CONV1 (C1_F_OFF + 16384)   // 99328

__global__ __launch_bounds__(256) void conv1_hmma_kernel(
    const float* __restrict__ X,   // x [NIMG][256][HW]
    const float* __restrict__ gg, const float* __restrict__ bb,
    const float* __restrict__ mm, const float* __restrict__ vv)
{
    extern __shared__ char smem[];
    const u32 sb = smem_u32(smem);
    const int tid = threadIdx.x;
    const int wid = tid >> 5;
    const int lane = tid & 31;
    const int hw0 = blockIdx.x * 64;
    const int img = blockIdx.y;
    const int m0 = (wid & 3) * 32;
    const int n0 = (wid >> 2) * 32;

    const u32 aLane = (u32)(((lane & 7) + (lane & 8)) * BSTR + ((lane >> 4) & 1) * 16);
    const u32 bLane4 = (u32)((lane & 7) * BSTR + ((lane >> 3) & 1) * 16
                             + ((lane >> 4) & 1) * 8 * BSTR);
    const int g = lane >> 2;
    const int t2 = lane & 3;

    float tot[2][4][4];
    float work[2][4][4];
#pragma unroll
    for (int a = 0; a < 2; a++)
#pragma unroll
        for (int n = 0; n < 4; n++)
#pragma unroll
            for (int d = 0; d < 4; d++) { tot[a][n][d] = 0.f; work[a][n][d] = 0.f; }

    // combo order per chunk: main first (flushed), corrections chained
    const int AI[6] = {0, 0, 1, 1, 0, 2};
    const int BJ[6] = {0, 1, 0, 1, 2, 0};

#pragma unroll 1
    for (int kc = 0; kc < 4; kc++) {
        __syncthreads();   // protect smem from previous chunk's reads
        // ---- load x fp32 chunk [64 k][64 px] into xor-swizzled staging ----
#pragma unroll
        for (int q = 0; q < 4; q++) {
            int f = tid + q * 256;       // 0..1023 float4 units
            int k = f >> 4, c4 = f & 15;
            float4 v4 = *(const float4*)&X[((size_t)img * CIN + kc * 64 + k) * HW + hw0 + c4 * 4];
            *(float4*)(smem + C1_F_OFF + k * 256 + ((c4 ^ (k & 15)) * 16)) = v4;
        }
        // ---- stage A chunk: 3 splits x 128 m x 64 k ----
#pragma unroll
        for (int q = 0; q < 12; q++) {
            int f = tid + q * 256;       // 0..3071
            int qq = f & 7;
            int row = f >> 3;            // 0..383
            int m = row & 127;
            int split = row >> 7;
            u32 dst = sb + split * C1_A_SPLIT + m * BSTR + qq * 16;
            const char* src = (const char*)g_w1s +
                ((((size_t)split * 4 + kc) * 128 + m) * 128 + qq * 16);
            cp16(dst, src, true);
        }
        cp_commit();
        __syncthreads();
        // ---- convert x chunk to bf16x3 [split][px][64k] ----
        {
            int px = tid & 63, kg = tid >> 6;    // kg 0..3, 16 k each
            u32 pr0 = 0, pr1 = 0, pr2 = 0;
#pragma unroll
            for (int i = 0; i < 16; i++) {
                int k = kg * 16 + i;
                float h = *(const float*)(smem + C1_F_OFF + k * 256 +
                                          (((px >> 2) ^ (k & 15)) * 16) + (px & 3) * 4);
                __nv_bfloat16 c0 = __float2bfloat16_rn(h);
                float r1 = h - __bfloat162float(c0);
                __nv_bfloat16 c1 = __float2bfloat16_rn(r1);
                float r2 = r1 - __bfloat162float(c1);
                __nv_bfloat16 c2 = __float2bfloat16_rn(r2);
                if ((i & 1) == 0) {
                    pr0 = *(u16*)&c0; pr1 = *(u16*)&c1; pr2 = *(u16*)&c2;
                } else {
                    int ko = k - 1;
                    u32 base = C1_B_OFF + px * BSTR + ko * 2;
                    *(u32*)(smem + base)                  = pr0 | ((u32)*(u16*)&c0 << 16);
                    *(u32*)(smem + base + C1_B_SPLIT)     = pr1 | ((u32)*(u16*)&c1 << 16);
                    *(u32*)(smem + base + 2 * C1_B_SPLIT) = pr2 | ((u32)*(u16*)&c2 << 16);
                }
            }
        }
        cp_wait0();
        __syncthreads();

        // ---- MMA: 6 combos x 4 ksteps ----
#pragma unroll 1
        for (int c = 0; c < 6; c++) {
            const int ai = AI[c], bj = BJ[c];
#pragma unroll
            for (int ks = 0; ks < 4; ks++) {
                u32 afr[2][4];
                u32 ab = sb + ai * C1_A_SPLIT + (u32)(m0 * BSTR) + aLane + ks * 32;
                ldm4(afr[0], ab);
                ldm4(afr[1], ab + 16 * BSTR);
                const u32 bbase = sb + C1_B_OFF + bj * C1_B_SPLIT + (u32)(ks * 32);
#pragma unroll
                for (int np = 0; np < 2; np++) {
                    u32 b4[4];
                    ldm4(b4, bbase + (u32)((n0 + np * 16) * BSTR) + bLane4);
                    mma16816(work[0][2 * np],     afr[0], b4);
                    mma16816(work[1][2 * np],     afr[1], b4);
                    mma16816(work[0][2 * np + 1], afr[0], b4 + 2);
                    mma16816(work[1][2 * np + 1], afr[1], b4 + 2);
                }
            }
            if (c == 0) {   // flush main term per chunk
#pragma unroll
                for (int a = 0; a < 2; a++)
#pragma unroll
                    for (int n = 0; n < 4; n++)
#pragma unroll
                        for (int d = 0; d < 4; d++) {
                            tot[a][n][d] += work[a][n][d];
                            work[a][n][d] = 0.f;
                        }
            }
        }
    }
    // final correction flush
#pragma unroll
    for (int a = 0; a < 2; a++)
#pragma unroll
        for (int n = 0; n < 4; n++)
#pragma unroll
            for (int d = 0; d < 4; d++) tot[a][n][d] += work[a][n][d];

    // ---- epilogue: BN, then bf16x3 split via smem transpose ----
    float scv[2][2], biv[2][2];
#pragma unroll
    for (int mt = 0; mt < 2; mt++)
#pragma unroll
        for (int h = 0; h < 2; h++) {
            int c = m0 + mt * 16 + g + h * 8;
            float sc = gg[c] / sqrtf(vv[c] + EPSBN);
            scv[mt][h] = sc;
            biv[mt][h] = bb[c] - mm[c] * sc;
        }
    // residual state in tot
#pragma unroll
    for (int mt = 0; mt < 2; mt++)
#pragma unroll
        for (int nt = 0; nt < 4; nt++)
#pragma unroll
            for (int d = 0; d < 4; d++)
                tot[mt][nt][d] = tot[mt][nt][d] * scv[mt][d >> 1] + biv[mt][d >> 1];

#pragma unroll 1
    for (int j = 0; j < 3; j++) {
        __syncthreads();
        // write split-j halves into smem [px 64][c 128]
#pragma unroll
        for (int mt = 0; mt < 2; mt++)
#pragma unroll
            for (int nt = 0; nt < 4; nt++)
#pragma unroll
                for (int d = 0; d < 4; d++) {
                    float r = tot[mt][nt][d];
                    __nv_bfloat16 bj = __float2bfloat16_rn(r);
                    tot[mt][nt][d] = r - __bfloat162float(bj);
                    int pxl = n0 + nt * 8 + 2 * t2 + (d & 1);
                    int c = m0 + mt * 16 + g + (d >> 1) * 8;
                    *(u16*)(smem + C1_F_OFF + (pxl * 128 + c) * 2) = *(u16*)&bj;
                }
        __syncthreads();
        // coalesced copy out: 16 uint4 per px row (128 c * 2B = 256B)
#pragma unroll
        for (int q = 0; q < 4; q++) {
            int u = tid + q * 256;       // 0..1023 uint4
            int px = u >> 4, c8 = (u & 15) * 8;
            *(uint4*)&g_h1s[(size_t)j * HSPLIT +
                            ((size_t)img * HW + hw0 + px) * 128 + c8] =
                *(uint4*)(smem + C1_F_OFF + u * 16);
        }
    }
}

// ---------------------------------------------------------------------------
// conv2: 3x3 128->128 + BN via mma.sync bf16x3 (round 6 EXACT: 2-row blocks,
// ldm2 B-fragment loads, Ootomo flush discipline — fastest measured conv2).
// ---------------------------------------------------------------------------
#define SB_ROW (58 * BSTR)            // 8352
#define SB_SPLIT_SZ (4 * SB_ROW)      // 33408
#define A_OFF (3 * SB_SPLIT_SZ)       // 100224
#define A_BUFSZ (128 * BSTR)          // 18432
#define SMEM_CONV2 (A_OFF + 2 * A_BUFSZ)   // 137088

__device__ __forceinline__ void sched36(int it, int& split, int& tap, int& bjs, int& nbj) {
    if (it < 9)       { split = 0; tap = it;      bjs = 0; nbj = 1; }   // main
    else if (it < 18) { split = 0; tap = it - 9;  bjs = 1; nbj = 2; }   // a0b1, a0b2
    else if (it < 27) { split = 1; tap = it - 18; bjs = 0; nbj = 2; }   // a1b0, a1b1
    else              { split = 2; tap = it - 27; bjs = 0; nbj = 1; }   // a2b0
}

__global__ __launch_bounds__(256) void conv2_hmma_kernel(
    const float* __restrict__ gg, const float* __restrict__ bb,
    const float* __restrict__ mm, const float* __restrict__ vv)
{
    extern __shared__ char smem[];
    const u32 sb = smem_u32(smem);
    const int tid = threadIdx.x;
    const int wid = tid >> 5;
    const int lane = tid & 31;
    const int img = blockIdx.y;
    const int y0 = blockIdx.x * 2;
    const int m0 = (wid & 3) * 32;    // warp M offset
    const int nw = wid >> 2;          // warp output row (0 or 1)

    float totals[2][7][4];
    float work[2][7][4];
#pragma unroll
    for (int a = 0; a < 2; a++)
#pragma unroll
        for (int n = 0; n < 7; n++)
#pragma unroll
            for (int d = 0; d < 4; d++) { totals[a][n][d] = 0.f; work[a][n][d] = 0.f; }

    const u32 aLane = (u32)(((lane & 7) + (lane & 8)) * BSTR + ((lane >> 4) & 1) * 16);
    const u32 bLane = (u32)((lane & 7) * BSTR + ((lane >> 3) & 1) * 16);

    for (int kh = 0; kh < 2; kh++) {
        // ---- stage B: 3 splits x 4 input rows x 58 px x 64 halves ----
        for (int f = tid; f < 3 * 4 * 58 * 8; f += 256) {
            int q = f & 7;
            int p = f >> 3;
            int px = p % 58;
            int t = p / 58;
            int ri = t & 3;
            int split = t >> 2;
            int y = y0 - 1 + ri;
            int x = px - 1;
            bool valid = ((unsigned)y < (unsigned)HDIM) && ((unsigned)x < (unsigned)HDIM);
            u32 dst = sb + split * SB_SPLIT_SZ + ri * SB_ROW + px * BSTR + q * 16;
            const char* src = (const char*)g_h1s +
                (((size_t)split * HSPLIT +
                  (((size_t)img * HW + (valid ? (y * HDIM + x) : 0)) * 128 + kh * 64 + q * 8)) << 1);
            cp16(dst, src, valid);
        }
        cp_commit();
        {   // A tile for it=0 (tap0, split0)
            const char* tbase = (const char*)g_w2a + ((size_t)(0 * 3 + 0) * 2 + kh) * 8192 * 2;
#pragma unroll
            for (int q = 0; q < 4; q++) {
                int f = tid + q * 256;
                cp16(sb + A_OFF + (f >> 3) * BSTR + (f & 7) * 16, tbase + (size_t)f * 16, true);
            }
            cp_commit();
        }
        cp_wait0();
        __syncthreads();

#pragma unroll 1
        for (int it = 0; it < 36; it++) {
            if (it < 35) {
                int nsplit, ntap, nbjs, nnbj;
                sched36(it + 1, nsplit, ntap, nbjs, nnbj);
                const char* tbase = (const char*)g_w2a +
                    ((size_t)((ntap * 3 + nsplit) * 2 + kh) * 8192) * 2;
                u32 abase = sb + A_OFF + ((it + 1) & 1) * A_BUFSZ;
#pragma unroll
                for (int q = 0; q < 4; q++) {
                    int f = tid + q * 256;
                    cp16(abase + (f >> 3) * BSTR + (f & 7) * 16, tbase + (size_t)f * 16, true);
                }
                cp_commit();
            }
            int split, tap, bjs, nbj;
            sched36(it, split, tap, bjs, nbj);
            const int r = tap / 3;
            const int s = tap - r * 3;
            const int ri = nw + r;
            const u32 ab = sb + A_OFF + (it & 1) * A_BUFSZ;

#pragma unroll
            for (int ks = 0; ks < 4; ks++) {
                u32 afr[2][4];
                ldm4(afr[0], ab + (u32)(m0 * BSTR) + aLane + ks * 32);
                ldm4(afr[1], ab + (u32)((m0 + 16) * BSTR) + aLane + ks * 32);
#pragma unroll 1
                for (int j = 0; j < nbj; j++) {
                    const u32 bbase = sb + (bjs + j) * SB_SPLIT_SZ + ri * SB_ROW
                                      + (u32)(ks * 32) + bLane;
#pragma unroll
                    for (int nt = 0; nt < 7; nt++) {
                        u32 bfr[2];
                        ldm2(bfr, bbase + (nt * 8 + s) * BSTR);
                        mma16816(work[0][nt], afr[0], bfr);
                        mma16816(work[1][nt], afr[1], bfr);
                    }
                }
            }
            cp_wait0();
            __syncthreads();
            if (it < 9 || it == 35) {
#pragma unroll
                for (int a = 0; a < 2; a++)
#pragma unroll
                    for (int n = 0; n < 7; n++)
#pragma unroll
                        for (int d = 0; d < 4; d++) {
                            totals[a][n][d] += work[a][n][d];
                            work[a][n][d] = 0.f;
                        }
            }
        }
    }

    // ---- epilogue: BN + store fp32 to g_h2 [img][c][hw] ----
    const int g = lane >> 2;
    const int t2 = lane & 3;
    float scv[2][2], biv[2][2];
#pragma unroll
    for (int mt = 0; mt < 2; mt++)
#pragma unroll
        for (int h = 0; h < 2; h++) {
            int c = m0 + mt * 16 + g + h * 8;
            float sc = gg[c] / sqrtf(vv[c] + EPSBN);
            scv[mt][h] = sc;
            biv[mt][h] = bb[c] - mm[c] * sc;
        }
    float* outimg = g_h2 + (size_t)img * CH * HW;
    const int yo = y0 + nw;
#pragma unroll
    for (int nt = 0; nt < 7; nt++) {
        int xo = nt * 8 + 2 * t2;
#pragma unroll
        for (int mt = 0; mt < 2; mt++) {
            int clo = m0 + mt * 16 + g;
            float2 vlo = make_float2(totals[mt][nt][0] * scv[mt][0] + biv[mt][0],
                                     totals[mt][nt][1] * scv[mt][0] + biv[mt][0]);
            float2 vhi = make_float2(totals[mt][nt][2] * scv[mt][1] + biv[mt][1],
                                     totals[mt][nt][3] * scv[mt][1] + biv[mt][1]);
            *(float2*)&outimg[(size_t)clo * HW + yo * HDIM + xo] = vlo;
            *(float2*)&outimg[(size_t)(clo + 8) * HW + yo * HDIM + xo] = vhi;
        }
    }
}

// ---------------------------------------------------------------------------
// conv3 + BN + LIF fused, bf16x3 6-term (round 6, proven).
// grid (49 hw-tiles of 64 px, 16 batch, 2 cb). 256 thr = 8 warps (4M x 2N).
// ---------------------------------------------------------------------------
#define C3_A_SPLIT 36864      // 2 kh * 128 m * 144
#define C3_A_KH    18432
#define C3_B_OFF   110592     // 3 * C3_A_SPLIT
#define C3_B_SPLIT 18432      // 2 kh * 64 px * 144
#define C3_B_KH    9216
#define C3_F_OFF   165888     // fp32 staging, 32KB, xor-swizzled float4s
#define SMEM_CONV3 (C3_F_OFF + 32768)   // 198656

__global__ __launch_bounds__(256) void conv3_lif_kernel(
    const float* __restrict__ gg, const float* __restrict__ bb,
    const float* __restrict__ mm, const float* __restrict__ vv,
    float* __restrict__ out)
{
    extern __shared__ char smem[];
    const u32 sb = smem_u32(smem);
    const int tid = threadIdx.x;
    const int wid = tid >> 5;
    const int lane = tid & 31;
    const int hw0 = blockIdx.x * 64;
    const int bidx = blockIdx.y;
    const int cb = blockIdx.z;
    const int m0 = (wid & 3) * 32;
    const int n0 = (wid >> 2) * 32;

    // ---- stage A once: 3 splits x 2 kh x 128 m x 128B (144B stride) ----
    for (int f = tid; f < 6144; f += 256) {
        int q = f & 7;
        int row = f >> 3;              // 0..767
        int m = row & 127;
        int kh = (row >> 7) & 1;
        int split = row >> 8;
        u32 dst = sb + split * C3_A_SPLIT + kh * C3_A_KH + m * BSTR + q * 16;
        const char* src = (const char*)g_w3s +
            ((((size_t)(cb * 3 + split) * 2 + kh) * 128 + m) * 128 + q * 16);
        cp16(dst, src, true);
    }
    cp_commit();

    const u32 aLane = (u32)(((lane & 7) + (lane & 8)) * BSTR + ((lane >> 4) & 1) * 16);
    const u32 bLane4 = (u32)((lane & 7) * BSTR + ((lane >> 3) & 1) * 16
                             + ((lane >> 4) & 1) * 8 * BSTR);
    const int g = lane >> 2;
    const int t2 = lane & 3;

    float scv[2][2], biv[2][2];
#pragma unroll
    for (int mt = 0; mt < 2; mt++)
#pragma unroll
        for (int h = 0; h < 2; h++) {
            int c = cb * 128 + m0 + mt * 16 + g + h * 8;
            float sc = gg[c] / sqrtf(vv[c] + EPSBN);
            scv[mt][h] = sc;
            biv[mt][h] = bb[c] - mm[c] * sc;
        }

    float vst[2][4][4];
#pragma unroll
    for (int a = 0; a < 2; a++)
#pragma unroll
        for (int n = 0; n < 4; n++)
#pragma unroll
            for (int d = 0; d < 4; d++) vst[a][n][d] = 0.f;

    // combo order: corrections first (acc small -> RZ harmless), main last
    const int AI[6] = {0, 0, 1, 1, 2, 0};
    const int BJ[6] = {1, 2, 0, 1, 0, 0};

#pragma unroll 1
    for (int t = 0; t < T_STEPS; t++) {
        const int img = t * BATCH + bidx;
        __syncthreads();   // protect B smem from previous iteration's reads

        // ---- load h2 fp32 tile [k=128][px=64] into xor-swizzled staging ----
#pragma unroll
        for (int q = 0; q < 8; q++) {
            int f = tid + q * 256;
            int k = f >> 4, c4 = f & 15;
            float4 v4 = *(const float4*)&g_h2[((size_t)img * CH + k) * HW + hw0 + c4 * 4];
            *(float4*)(smem + C3_F_OFF + k * 256 + ((c4 ^ (k & 15)) * 16)) = v4;
        }
        __syncthreads();

        // ---- convert to bf16x3 [split][kh][px][64k] ----
        {
            int px = tid & 63, kg = tid >> 6;    // kg 0..3
            u32 pr0 = 0, pr1 = 0, pr2 = 0;
#pragma unroll
            for (int i = 0; i < 32; i++) {
                int k = kg * 32 + i;
                float h = *(const float*)(smem + C3_F_OFF + k * 256 +
                                          (((px >> 2) ^ (k & 15)) * 16) + (px & 3) * 4);
                __nv_bfloat16 c0 = __float2bfloat16_rn(h);
                float r1 = h - __bfloat162float(c0);
                __nv_bfloat16 c1 = __float2bfloat16_rn(r1);
                float r2 = r1 - __bfloat162float(c1);
                __nv_bfloat16 c2 = __float2bfloat16_rn(r2);
                if ((i & 1) == 0) {
                    pr0 = *(u16*)&c0; pr1 = *(u16*)&c1; pr2 = *(u16*)&c2;
                } else {
                    int kh = k >> 6, ko = (k & 63) - 1;
                    u32 base = C3_B_OFF + kh * C3_B_KH + px * BSTR + ko * 2;
                    *(u32*)(smem + base)                  = pr0 | ((u32)*(u16*)&c0 << 16);
                    *(u32*)(smem + base + C3_B_SPLIT)     = pr1 | ((u32)*(u16*)&c1 << 16);
                    *(u32*)(smem + base + 2 * C3_B_SPLIT) = pr2 | ((u32)*(u16*)&c2 << 16);
                }
            }
        }
        if (t == 0) cp_wait0();    // A tiles arrived
        __syncthreads();

        float tot[2][4][4];
#pragma unroll
        for (int a = 0; a < 2; a++)
#pragma unroll
            for (int n = 0; n < 4; n++)
#pragma unroll
                for (int d = 0; d < 4; d++) tot[a][n][d] = 0.f;

        // corrections (combos 0-4) chained, flushed once; then main chained
        float acc[2][4][4];
#pragma unroll
        for (int a = 0; a < 2; a++)
#pragma unroll
            for (int n = 0; n < 4; n++)
#pragma unroll
                for (int d = 0; d < 4; d++) acc[a][n][d] = 0.f;

#pragma unroll 1
        for (int c = 0; c < 6; c++) {
            const int ai = AI[c], bj = BJ[c];
#pragma unroll
            for (int kh = 0; kh < 2; kh++) {
#pragma unroll
                for (int ks = 0; ks < 4; ks++) {
                    u32 afr[2][4];
                    u32 ab = sb + ai * C3_A_SPLIT + kh * C3_A_KH + (u32)(m0 * BSTR)
                             + aLane + ks * 32;
                    ldm4(afr[0], ab);
                    ldm4(afr[1], ab + 16 * BSTR);
                    const u32 bbase = sb + C3_B_OFF + bj * C3_B_SPLIT + kh * C3_B_KH
                                      + (u32)(ks * 32);
#pragma unroll
                    for (int np = 0; np < 2; np++) {
                        u32 b4[4];
                        ldm4(b4, bbase + (u32)((n0 + np * 16) * BSTR) + bLane4);
                        mma16816(acc[0][2 * np],     afr[0], b4);
                        mma16816(acc[1][2 * np],     afr[1], b4);
                        mma16816(acc[0][2 * np + 1], afr[0], b4 + 2);
                        mma16816(acc[1][2 * np + 1], afr[1], b4 + 2);
                    }
                }
            }
            if (c == 4) {   // flush corrections before the main term
#pragma unroll
                for (int a = 0; a < 2; a++)
#pragma unroll
                    for (int n = 0; n < 4; n++)
#pragma unroll
                        for (int d = 0; d < 4; d++) {
                            tot[a][n][d] += acc[a][n][d];
                            acc[a][n][d] = 0.f;
                        }
            }
        }
#pragma unroll
        for (int a = 0; a < 2; a++)
#pragma unroll
            for (int n = 0; n < 4; n++)
#pragma unroll
                for (int d = 0; d < 4; d++) tot[a][n][d] += acc[a][n][d];

        // ---- epilogue: BN + LIF + store spikes ----
#pragma unroll
        for (int nt = 0; nt < 4; nt++) {
            int n = n0 + nt * 8 + 2 * t2;
#pragma unroll
            for (int mt = 0; mt < 2; mt++) {
                int clo = cb * 128 + m0 + mt * 16 + g;
                float s[4];
#pragma unroll
                for (int d = 0; d < 4; d++) {
                    int h = d >> 1;
                    float h3 = tot[mt][nt][d] * scv[mt][h] + biv[mt][h];
                    float v = vst[mt][nt][d];
                    v = v + (h3 - v) * 0.5f;
                    float sp = (v >= 1.0f) ? 1.0f : 0.0f;
                    s[d] = sp;
                    vst[mt][nt][d] = v * (1.0f - sp);
                }
                *(float2*)&out[((size_t)img * COUT + clo) * HW + hw0 + n] =
                    make_float2(s[0], s[1]);
                *(float2*)&out[((size_t)img * COUT + clo + 8) * HW + hw0 + n] =
                    make_float2(s[2], s[3]);
            }
        }
    }
}

// ---------------------------------------------------------------------------
extern "C" void kernel_launch(void* const* d_in, const int* in_sizes, int n_in,
                              void* d_out, int out_size)
{
    const float* x  = (const float*)d_in[0];
    const float* w1 = (const float*)d_in[1];
    const float* g1 = (const float*)d_in[2];
    const float* b1 = (const float*)d_in[3];
    const float* m1 = (const float*)d_in[4];
    const float* v1 = (const float*)d_in[5];
    const float* w2 = (const float*)d_in[6];
    const float* g2 = (const float*)d_in[7];
    const float* b2 = (const float*)d_in[8];
    const float* m2 = (const float*)d_in[9];
    const float* v2 = (const float*)d_in[10];
    const float* w3 = (const float*)d_in[11];
    const float* g3 = (const float*)d_in[12];
    const float* b3 = (const float*)d_in[13];
    const float* m3 = (const float*)d_in[14];
    const float* v3 = (const float*)d_in[15];
    float* out = (float*)d_out;

    cudaFuncSetAttribute(conv1_hmma_kernel,
                         cudaFuncAttributeMaxDynamicSharedMemorySize, SMEM_CONV1);
    cudaFuncSetAttribute(conv2_hmma_kernel,
                         cudaFuncAttributeMaxDynamicSharedMemorySize, SMEM_CONV2);
    cudaFuncSetAttribute(conv3_lif_kernel,
                         cudaFuncAttributeMaxDynamicSharedMemorySize, SMEM_CONV3);

    // weight splits
    prep_w1s_kernel<<<(128 * 256 + 255) / 256, 256>>>(w1);
    prep_w2a_kernel<<<(9 * 128 * 128 + 255) / 256, 256>>>(w2);
    prep_w3s_kernel<<<(256 * 128 + 255) / 256, 256>>>(w3);

    // conv1: 1x1 256->128 + BN1 via HMMA -> bf16x3 channel-last splits
    conv1_hmma_kernel<<<dim3(49, NIMG), 256, SMEM_CONV1>>>(x, g1, b1, m1, v1);

    // conv2: 3x3 128->128 + BN2 via mma.sync (round-6 exact) -> g_h2
    conv2_hmma_kernel<<<dim3(28, NIMG), 256, SMEM_CONV2>>>(g2, b2, m2, v2);

    // conv3 + BN3 + LIF fused -> d_out spikes
    conv3_lif_kernel<<<dim3(49, BATCH, 2), 256, SMEM_CONV3>>>(g3, b3, m3, v3, out);
}

// round 13
// speedup vs baseline: 1.0773x; 1.0399x over previous
#include <cuda_runtime.h>
#include <cuda_bf16.h>
#include <cstdint>

// Problem dims (fixed)
#define T_STEPS 4
#define BATCH   16
#define NIMG    64          // T*B
#define CIN     256
#define CH      128
#define COUT    256
#define HDIM    56
#define HW      3136        // 56*56 = 49*64
#define EPSBN   1e-5f

typedef unsigned long long u64;
typedef unsigned int u32;
typedef unsigned short u16;

// ------------------------- device scratch (no malloc allowed) ---------------
#define HSPLIT ((size_t)NIMG * HW * 128)           // elements per split tensor
__device__ __nv_bfloat16 g_h1s[3 * HSPLIT];        // h1 bf16 splits, channel-last
__device__ __nv_bfloat16 g_h2s[3 * HSPLIT];        // h2 bf16 splits, channel-last
// w1 bf16 splits: [split 3][kq 4][m 128][64 halves]
__device__ __nv_bfloat16 g_w1s[3 * 4 * 128 * 64];
// w2 bf16 splits: [rs 9][split 3][kh 2][m 128][64 halves]
__device__ __nv_bfloat16 g_w2a[9 * 3 * 2 * 128 * 64];
// w3 bf16 splits: [cb 2][split 3][kh 2][m 128][64 halves]
__device__ __nv_bfloat16 g_w3s[2 * 3 * 2 * 128 * 64];

// ---------------------------- mma.sync helpers ------------------------------
__device__ __forceinline__ u32 smem_u32(const void* p) {
    u32 a; asm("{ .reg .u64 t; cvta.to.shared.u64 t, %1; cvt.u32.u64 %0, t; }" : "=r"(a) : "l"(p));
    return a;
}
__device__ __forceinline__ void ldm4(u32* r, u32 addr) {
    asm volatile("ldmatrix.sync.aligned.m8n8.x4.shared.b16 {%0,%1,%2,%3}, [%4];"
        : "=r"(r[0]), "=r"(r[1]), "=r"(r[2]), "=r"(r[3]) : "r"(addr));
}
__device__ __forceinline__ void ldm2(u32* r, u32 addr) {
    asm volatile("ldmatrix.sync.aligned.m8n8.x2.shared.b16 {%0,%1}, [%2];"
        : "=r"(r[0]), "=r"(r[1]) : "r"(addr));
}
__device__ __forceinline__ void mma16816(float* d, const u32* a, const u32* b) {
    asm volatile("mma.sync.aligned.m16n8k16.row.col.f32.bf16.bf16.f32 "
        "{%0,%1,%2,%3}, {%4,%5,%6,%7}, {%8,%9}, {%0,%1,%2,%3};"
        : "+f"(d[0]), "+f"(d[1]), "+f"(d[2]), "+f"(d[3])
        : "r"(a[0]), "r"(a[1]), "r"(a[2]), "r"(a[3]), "r"(b[0]), "r"(b[1]));
}
__device__ __forceinline__ void cp16(u32 dst, const void* src, bool valid) {
    int sz = valid ? 16 : 0;
    asm volatile("cp.async.cg.shared.global [%0], [%1], 16, %2;"
                 :: "r"(dst), "l"(src), "r"(sz) : "memory");
}
__device__ __forceinline__ void cp_commit() {
    asm volatile("cp.async.commit_group;" ::: "memory");
}
__device__ __forceinline__ void cp_wait0() {
    asm volatile("cp.async.wait_group 0;" ::: "memory");
}

#define BSTR 144                      // bytes per 64-half row (128B + 16 pad)

// ---------------------------------------------------------------------------
// prep: w1 ([128][256]) -> bf16x3 splits [split 3][kq 4][m 128][64]
// ---------------------------------------------------------------------------
__global__ void prep_w1s_kernel(const float* __restrict__ w1) {
    int idx = blockIdx.x * blockDim.x + threadIdx.x;
    if (idx >= 128 * 256) return;
    int k = idx & 255;
    int m = idx >> 8;
    float w = w1[(size_t)m * 256 + k];
    __nv_bfloat16 b0 = __float2bfloat16_rn(w);
    float r1 = w - __bfloat162float(b0);
    __nv_bfloat16 b1 = __float2bfloat16_rn(r1);
    float r2 = r1 - __bfloat162float(b1);
    __nv_bfloat16 b2 = __float2bfloat16_rn(r2);
    int kq = k >> 6, ko = k & 63;
    size_t base = (((size_t)kq * 128) + m) * 64 + ko;
    size_t sstep = (size_t)4 * 128 * 64;
    g_w1s[base]             = b0;
    g_w1s[base + sstep]     = b1;
    g_w1s[base + 2 * sstep] = b2;
}

// ---------------------------------------------------------------------------
// prep: w2 (OIHW [128][128][3][3]) -> bf16x3 splits [rs][split][kh][m][64]
// ---------------------------------------------------------------------------
__global__ void prep_w2a_kernel(const float* __restrict__ w2) {
    int idx = blockIdx.x * blockDim.x + threadIdx.x;
    if (idx >= 9 * 128 * 128) return;
    int k = idx & 127;
    int m = (idx >> 7) & 127;
    int rs = idx >> 14;
    float w = w2[((size_t)(m * 128 + k)) * 9 + rs];
    __nv_bfloat16 b0 = __float2bfloat16_rn(w);
    float r1 = w - __bfloat162float(b0);
    __nv_bfloat16 b1 = __float2bfloat16_rn(r1);
    float r2 = r1 - __bfloat162float(b1);
    __nv_bfloat16 b2 = __float2bfloat16_rn(r2);
    int kh = k >> 6, ko = k & 63;
    size_t base = ((((size_t)rs * 3) * 2 + kh) * 128 + m) * 64 + ko;
    size_t sstep = (size_t)2 * 128 * 64;   // stride between splits
    g_w2a[base]             = b0;
    g_w2a[base + sstep]     = b1;
    g_w2a[base + 2 * sstep] = b2;
}

// ---------------------------------------------------------------------------
// prep: w3 ([256][128]) -> bf16x3 splits [cb 2][split 3][kh 2][m 128][64]
// ---------------------------------------------------------------------------
__global__ void prep_w3s_kernel(const float* __restrict__ w3) {
    int idx = blockIdx.x * blockDim.x + threadIdx.x;
    if (idx >= 256 * 128) return;
    int k = idx & 127;
    int mg = idx >> 7;            // 0..255
    int cb = mg >> 7, m = mg & 127;
    float w = w3[(size_t)mg * 128 + k];
    __nv_bfloat16 b0 = __float2bfloat16_rn(w);
    float r1 = w - __bfloat162float(b0);
    __nv_bfloat16 b1 = __float2bfloat16_rn(r1);
    float r2 = r1 - __bfloat162float(b1);
    __nv_bfloat16 b2 = __float2bfloat16_rn(r2);
    int kh = k >> 6, ko = k & 63;
    size_t sstep = (size_t)2 * 128 * 64;
    size_t base = ((((size_t)cb * 3) * 2 + kh) * 128 + m) * 64 + ko;
    g_w3s[base]             = b0;
    g_w3s[base + sstep]     = b1;
    g_w3s[base + 2 * sstep] = b2;
}

// ---------------------------------------------------------------------------
// conv1: 1x1 256->128 + BN via mma.sync bf16x3 6-term. (round 10, 318us, proven)
// ---------------------------------------------------------------------------
#define C1_A_SPLIT 18432     // 128 m * 144
#define C1_B_OFF   55296     // 3 * C1_A_SPLIT
#define C1_B_SPLIT 9216      // 64 px * 144
#define C1_F_OFF   82944     // fp32 staging 64k x 64px = 16KB (xor-swizzled)
#define SMEM_CONV1 (C1_F_OFF + 16384)   // 99328

__global__ __launch_bounds__(256) void conv1_hmma_kernel(
    const float* __restrict__ X,   // x [NIMG][256][HW]
    const float* __restrict__ gg, const float* __restrict__ bb,
    const float* __restrict__ mm, const float* __restrict__ vv)
{
    extern __shared__ char smem[];
    const u32 sb = smem_u32(smem);
    const int tid = threadIdx.x;
    const int wid = tid >> 5;
    const int lane = tid & 31;
    const int hw0 = blockIdx.x * 64;
    const int img = blockIdx.y;
    const int m0 = (wid & 3) * 32;
    const int n0 = (wid >> 2) * 32;

    const u32 aLane = (u32)(((lane & 7) + (lane & 8)) * BSTR + ((lane >> 4) & 1) * 16);
    const u32 bLane4 = (u32)((lane & 7) * BSTR + ((lane >> 3) & 1) * 16
                             + ((lane >> 4) & 1) * 8 * BSTR);
    const int g = lane >> 2;
    const int t2 = lane & 3;

    float tot[2][4][4];
    float work[2][4][4];
#pragma unroll
    for (int a = 0; a < 2; a++)
#pragma unroll
        for (int n = 0; n < 4; n++)
#pragma unroll
            for (int d = 0; d < 4; d++) { tot[a][n][d] = 0.f; work[a][n][d] = 0.f; }

    // combo order per chunk: main first (flushed), corrections chained
    const int AI[6] = {0, 0, 1, 1, 0, 2};
    const int BJ[6] = {0, 1, 0, 1, 2, 0};

#pragma unroll 1
    for (int kc = 0; kc < 4; kc++) {
        __syncthreads();   // protect smem from previous chunk's reads
        // ---- load x fp32 chunk [64 k][64 px] into xor-swizzled staging ----
#pragma unroll
        for (int q = 0; q < 4; q++) {
            int f = tid + q * 256;       // 0..1023 float4 units
            int k = f >> 4, c4 = f & 15;
            float4 v4 = *(const float4*)&X[((size_t)img * CIN + kc * 64 + k) * HW + hw0 + c4 * 4];
            *(float4*)(smem + C1_F_OFF + k * 256 + ((c4 ^ (k & 15)) * 16)) = v4;
        }
        // ---- stage A chunk: 3 splits x 128 m x 64 k ----
#pragma unroll
        for (int q = 0; q < 12; q++) {
            int f = tid + q * 256;       // 0..3071
            int qq = f & 7;
            int row = f >> 3;            // 0..383
            int m = row & 127;
            int split = row >> 7;
            u32 dst = sb + split * C1_A_SPLIT + m * BSTR + qq * 16;
            const char* src = (const char*)g_w1s +
                ((((size_t)split * 4 + kc) * 128 + m) * 128 + qq * 16);
            cp16(dst, src, true);
        }
        cp_commit();
        __syncthreads();
        // ---- convert x chunk to bf16x3 [split][px][64k] ----
        {
            int px = tid & 63, kg = tid >> 6;    // kg 0..3, 16 k each
            u32 pr0 = 0, pr1 = 0, pr2 = 0;
#pragma unroll
            for (int i = 0; i < 16; i++) {
                int k = kg * 16 + i;
                float h = *(const float*)(smem + C1_F_OFF + k * 256 +
                                          (((px >> 2) ^ (k & 15)) * 16) + (px & 3) * 4);
                __nv_bfloat16 c0 = __float2bfloat16_rn(h);
                float r1 = h - __bfloat162float(c0);
                __nv_bfloat16 c1 = __float2bfloat16_rn(r1);
                float r2 = r1 - __bfloat162float(c1);
                __nv_bfloat16 c2 = __float2bfloat16_rn(r2);
                if ((i & 1) == 0) {
                    pr0 = *(u16*)&c0; pr1 = *(u16*)&c1; pr2 = *(u16*)&c2;
                } else {
                    int ko = k - 1;
                    u32 base = C1_B_OFF + px * BSTR + ko * 2;
                    *(u32*)(smem + base)                  = pr0 | ((u32)*(u16*)&c0 << 16);
                    *(u32*)(smem + base + C1_B_SPLIT)     = pr1 | ((u32)*(u16*)&c1 << 16);
                    *(u32*)(smem + base + 2 * C1_B_SPLIT) = pr2 | ((u32)*(u16*)&c2 << 16);
                }
            }
        }
        cp_wait0();
        __syncthreads();

        // ---- MMA: 6 combos x 4 ksteps ----
#pragma unroll 1
        for (int c = 0; c < 6; c++) {
            const int ai = AI[c], bj = BJ[c];
#pragma unroll
            for (int ks = 0; ks < 4; ks++) {
                u32 afr[2][4];
                u32 ab = sb + ai * C1_A_SPLIT + (u32)(m0 * BSTR) + aLane + ks * 32;
                ldm4(afr[0], ab);
                ldm4(afr[1], ab + 16 * BSTR);
                const u32 bbase = sb + C1_B_OFF + bj * C1_B_SPLIT + (u32)(ks * 32);
#pragma unroll
                for (int np = 0; np < 2; np++) {
                    u32 b4[4];
                    ldm4(b4, bbase + (u32)((n0 + np * 16) * BSTR) + bLane4);
                    mma16816(work[0][2 * np],     afr[0], b4);
                    mma16816(work[1][2 * np],     afr[1], b4);
                    mma16816(work[0][2 * np + 1], afr[0], b4 + 2);
                    mma16816(work[1][2 * np + 1], afr[1], b4 + 2);
                }
            }
            if (c == 0) {   // flush main term per chunk
#pragma unroll
                for (int a = 0; a < 2; a++)
#pragma unroll
                    for (int n = 0; n < 4; n++)
#pragma unroll
                        for (int d = 0; d < 4; d++) {
                            tot[a][n][d] += work[a][n][d];
                            work[a][n][d] = 0.f;
                        }
            }
        }
    }
    // final correction flush
#pragma unroll
    for (int a = 0; a < 2; a++)
#pragma unroll
        for (int n = 0; n < 4; n++)
#pragma unroll
            for (int d = 0; d < 4; d++) tot[a][n][d] += work[a][n][d];

    // ---- epilogue: BN, then bf16x3 split via smem transpose ----
    float scv[2][2], biv[2][2];
#pragma unroll
    for (int mt = 0; mt < 2; mt++)
#pragma unroll
        for (int h = 0; h < 2; h++) {
            int c = m0 + mt * 16 + g + h * 8;
            float sc = gg[c] / sqrtf(vv[c] + EPSBN);
            scv[mt][h] = sc;
            biv[mt][h] = bb[c] - mm[c] * sc;
        }
    // residual state in tot
#pragma unroll
    for (int mt = 0; mt < 2; mt++)
#pragma unroll
        for (int nt = 0; nt < 4; nt++)
#pragma unroll
            for (int d = 0; d < 4; d++)
                tot[mt][nt][d] = tot[mt][nt][d] * scv[mt][d >> 1] + biv[mt][d >> 1];

#pragma unroll 1
    for (int j = 0; j < 3; j++) {
        __syncthreads();
        // write split-j halves into smem [px 64][c 128]
#pragma unroll
        for (int mt = 0; mt < 2; mt++)
#pragma unroll
            for (int nt = 0; nt < 4; nt++)
#pragma unroll
                for (int d = 0; d < 4; d++) {
                    float r = tot[mt][nt][d];
                    __nv_bfloat16 bj = __float2bfloat16_rn(r);
                    tot[mt][nt][d] = r - __bfloat162float(bj);
                    int pxl = n0 + nt * 8 + 2 * t2 + (d & 1);
                    int c = m0 + mt * 16 + g + (d >> 1) * 8;
                    *(u16*)(smem + C1_F_OFF + (pxl * 128 + c) * 2) = *(u16*)&bj;
                }
        __syncthreads();
        // coalesced copy out: 16 uint4 per px row (128 c * 2B = 256B)
#pragma unroll
        for (int q = 0; q < 4; q++) {
            int u = tid + q * 256;       // 0..1023 uint4
            int px = u >> 4, c8 = (u & 15) * 8;
            *(uint4*)&g_h1s[(size_t)j * HSPLIT +
                            ((size_t)img * HW + hw0 + px) * 128 + c8] =
                *(uint4*)(smem + C1_F_OFF + u * 16);
        }
    }
}

// ---------------------------------------------------------------------------
// conv2: 3x3 128->128 + BN via mma.sync bf16x3 (round 6 mainloop EXACT).
// NEW epilogue: BN -> bf16x3 split -> channel-last g_h2s (computed once here
// instead of twice in conv3). Bitwise-identical split values.
// ---------------------------------------------------------------------------
#define SB_ROW (58 * BSTR)            // 8352
#define SB_SPLIT_SZ (4 * SB_ROW)      // 33408
#define A_OFF (3 * SB_SPLIT_SZ)       // 100224
#define A_BUFSZ (128 * BSTR)          // 18432
#define SMEM_CONV2 (A_OFF + 2 * A_BUFSZ)   // 137088
#define C2E_STR 272                    // padded px row stride for epilogue buf

__device__ __forceinline__ void sched36(int it, int& split, int& tap, int& bjs, int& nbj) {
    if (it < 9)       { split = 0; tap = it;      bjs = 0; nbj = 1; }   // main
    else if (it < 18) { split = 0; tap = it - 9;  bjs = 1; nbj = 2; }   // a0b1, a0b2
    else if (it < 27) { split = 1; tap = it - 18; bjs = 0; nbj = 2; }   // a1b0, a1b1
    else              { split = 2; tap = it - 27; bjs = 0; nbj = 1; }   // a2b0
}

__global__ __launch_bounds__(256) void conv2_hmma_kernel(
    const float* __restrict__ gg, const float* __restrict__ bb,
    const float* __restrict__ mm, const float* __restrict__ vv)
{
    extern __shared__ char smem[];
    const u32 sb = smem_u32(smem);
    const int tid = threadIdx.x;
    const int wid = tid >> 5;
    const int lane = tid & 31;
    const int img = blockIdx.y;
    const int y0 = blockIdx.x * 2;
    const int m0 = (wid & 3) * 32;    // warp M offset
    const int nw = wid >> 2;          // warp output row (0 or 1)

    float totals[2][7][4];
    float work[2][7][4];
#pragma unroll
    for (int a = 0; a < 2; a++)
#pragma unroll
        for (int n = 0; n < 7; n++)
#pragma unroll
            for (int d = 0; d < 4; d++) { totals[a][n][d] = 0.f; work[a][n][d] = 0.f; }

    const u32 aLane = (u32)(((lane & 7) + (lane & 8)) * BSTR + ((lane >> 4) & 1) * 16);
    const u32 bLane = (u32)((lane & 7) * BSTR + ((lane >> 3) & 1) * 16);

    for (int kh = 0; kh < 2; kh++) {
        // ---- stage B: 3 splits x 4 input rows x 58 px x 64 halves ----
        for (int f = tid; f < 3 * 4 * 58 * 8; f += 256) {
            int q = f & 7;
            int p = f >> 3;
            int px = p % 58;
            int t = p / 58;
            int ri = t & 3;
            int split = t >> 2;
            int y = y0 - 1 + ri;
            int x = px - 1;
            bool valid = ((unsigned)y < (unsigned)HDIM) && ((unsigned)x < (unsigned)HDIM);
            u32 dst = sb + split * SB_SPLIT_SZ + ri * SB_ROW + px * BSTR + q * 16;
            const char* src = (const char*)g_h1s +
                (((size_t)split * HSPLIT +
                  (((size_t)img * HW + (valid ? (y * HDIM + x) : 0)) * 128 + kh * 64 + q * 8)) << 1);
            cp16(dst, src, valid);
        }
        cp_commit();
        {   // A tile for it=0 (tap0, split0)
            const char* tbase = (const char*)g_w2a + ((size_t)(0 * 3 + 0) * 2 + kh) * 8192 * 2;
#pragma unroll
            for (int q = 0; q < 4; q++) {
                int f = tid + q * 256;
                cp16(sb + A_OFF + (f >> 3) * BSTR + (f & 7) * 16, tbase + (size_t)f * 16, true);
            }
            cp_commit();
        }
        cp_wait0();
        __syncthreads();

#pragma unroll 1
        for (int it = 0; it < 36; it++) {
            if (it < 35) {
                int nsplit, ntap, nbjs, nnbj;
                sched36(it + 1, nsplit, ntap, nbjs, nnbj);
                const char* tbase = (const char*)g_w2a +
                    ((size_t)((ntap * 3 + nsplit) * 2 + kh) * 8192) * 2;
                u32 abase = sb + A_OFF + ((it + 1) & 1) * A_BUFSZ;
#pragma unroll
                for (int q = 0; q < 4; q++) {
                    int f = tid + q * 256;
                    cp16(abase + (f >> 3) * BSTR + (f & 7) * 16, tbase + (size_t)f * 16, true);
                }
                cp_commit();
            }
            int split, tap, bjs, nbj;
            sched36(it, split, tap, bjs, nbj);
            const int r = tap / 3;
            const int s = tap - r * 3;
            const int ri = nw + r;
            const u32 ab = sb + A_OFF + (it & 1) * A_BUFSZ;

#pragma unroll
            for (int ks = 0; ks < 4; ks++) {
                u32 afr[2][4];
                ldm4(afr[0], ab + (u32)(m0 * BSTR) + aLane + ks * 32);
                ldm4(afr[1], ab + (u32)((m0 + 16) * BSTR) + aLane + ks * 32);
#pragma unroll 1
                for (int j = 0; j < nbj; j++) {
                    const u32 bbase = sb + (bjs + j) * SB_SPLIT_SZ + ri * SB_ROW
                                      + (u32)(ks * 32) + bLane;
#pragma unroll
                    for (int nt = 0; nt < 7; nt++) {
                        u32 bfr[2];
                        ldm2(bfr, bbase + (nt * 8 + s) * BSTR);
                        mma16816(work[0][nt], afr[0], bfr);
                        mma16816(work[1][nt], afr[1], bfr);
                    }
                }
            }
            cp_wait0();
            __syncthreads();
            if (it < 9 || it == 35) {
#pragma unroll
                for (int a = 0; a < 2; a++)
#pragma unroll
                    for (int n = 0; n < 7; n++)
#pragma unroll
                        for (int d = 0; d < 4; d++) {
                            totals[a][n][d] += work[a][n][d];
                            work[a][n][d] = 0.f;
                        }
            }
        }
    }

    // ---- epilogue: BN, then bf16x3 split -> channel-last g_h2s ----
    const int g = lane >> 2;
    const int t2 = lane & 3;
    float scv[2][2], biv[2][2];
#pragma unroll
    for (int mt = 0; mt < 2; mt++)
#pragma unroll
        for (int h = 0; h < 2; h++) {
            int c = m0 + mt * 16 + g + h * 8;
            float sc = gg[c] / sqrtf(vv[c] + EPSBN);
            scv[mt][h] = sc;
            biv[mt][h] = bb[c] - mm[c] * sc;
        }
#pragma unroll
    for (int mt = 0; mt < 2; mt++)
#pragma unroll
        for (int nt = 0; nt < 7; nt++)
#pragma unroll
            for (int d = 0; d < 4; d++)
                totals[mt][nt][d] = totals[mt][nt][d] * scv[mt][d >> 1] + biv[mt][d >> 1];

    // buf: [row 2][px 56][c 128] u16 with padded row stride C2E_STR bytes
#pragma unroll 1
    for (int j = 0; j < 3; j++) {
        __syncthreads();
#pragma unroll
        for (int mt = 0; mt < 2; mt++)
#pragma unroll
            for (int nt = 0; nt < 7; nt++)
#pragma unroll
                for (int d = 0; d < 4; d++) {
                    float r = totals[mt][nt][d];
                    __nv_bfloat16 bj = __float2bfloat16_rn(r);
                    totals[mt][nt][d] = r - __bfloat162float(bj);
                    int px = nt * 8 + 2 * t2 + (d & 1);
                    int c = m0 + mt * 16 + g + (d >> 1) * 8;
                    *(u16*)(smem + (nw * 56 + px) * C2E_STR + c * 2) = *(u16*)&bj;
                }
        __syncthreads();
        // coalesced copy out: 112 px-rows x 16 uint4 (data bytes only)
#pragma unroll
        for (int q = 0; q < 7; q++) {
            int u = tid + q * 256;       // 0..1791
            int pr = u >> 4;             // 0..111
            int row = pr / 56, px = pr - row * 56;
            int c8 = (u & 15) * 8;
            *(uint4*)&g_h2s[(size_t)j * HSPLIT +
                            ((size_t)img * HW + (y0 + row) * HDIM + px) * 128 + c8] =
                *(uint4*)(smem + pr * C2E_STR + c8 * 2);
        }
    }
}

// ---------------------------------------------------------------------------
// conv3 + BN + LIF fused, bf16x3 6-term. B tiles now cp.async'd directly from
// pre-split g_h2s (no fp32 staging, no in-kernel conversion).
// grid (49 hw-tiles of 64 px, 16 batch, 2 cb). 256 thr = 8 warps (4M x 2N).
// ---------------------------------------------------------------------------
#define C3_A_SPLIT 36864      // 2 kh * 128 m * 144
#define C3_A_KH    18432
#define C3_B_OFF   110592     // 3 * C3_A_SPLIT
#define C3_B_SPLIT 18432      // 2 kh * 64 px * 144
#define C3_B_KH    9216
#define SMEM_CONV3 (C3_B_OFF + 3 * C3_B_SPLIT)   // 165888

__global__ __launch_bounds__(256) void conv3_lif_kernel(
    const float* __restrict__ gg, const float* __restrict__ bb,
    const float* __restrict__ mm, const float* __restrict__ vv,
    float* __restrict__ out)
{
    extern __shared__ char smem[];
    const u32 sb = smem_u32(smem);
    const int tid = threadIdx.x;
    const int wid = tid >> 5;
    const int lane = tid & 31;
    const int hw0 = blockIdx.x * 64;
    const int bidx = blockIdx.y;
    const int cb = blockIdx.z;
    const int m0 = (wid & 3) * 32;
    const int n0 = (wid >> 2) * 32;

    // ---- stage A once: 3 splits x 2 kh x 128 m x 128B (144B stride) ----
    for (int f = tid; f < 6144; f += 256) {
        int q = f & 7;
        int row = f >> 3;              // 0..767
        int m = row & 127;
        int kh = (row >> 7) & 1;
        int split = row >> 8;
        u32 dst = sb + split * C3_A_SPLIT + kh * C3_A_KH + m * BSTR + q * 16;
        const char* src = (const char*)g_w3s +
            ((((size_t)(cb * 3 + split) * 2 + kh) * 128 + m) * 128 + q * 16);
        cp16(dst, src, true);
    }
    cp_commit();

    const u32 aLane = (u32)(((lane & 7) + (lane & 8)) * BSTR + ((lane >> 4) & 1) * 16);
    const u32 bLane4 = (u32)((lane & 7) * BSTR + ((lane >> 3) & 1) * 16
                             + ((lane >> 4) & 1) * 8 * BSTR);
    const int g = lane >> 2;
    const int t2 = lane & 3;

    float scv[2][2], biv[2][2];
#pragma unroll
    for (int mt = 0; mt < 2; mt++)
#pragma unroll
        for (int h = 0; h < 2; h++) {
            int c = cb * 128 + m0 + mt * 16 + g + h * 8;
            float sc = gg[c] / sqrtf(vv[c] + EPSBN);
            scv[mt][h] = sc;
            biv[mt][h] = bb[c] - mm[c] * sc;
        }

    float vst[2][4][4];
#pragma unroll
    for (int a = 0; a < 2; a++)
#pragma unroll
        for (int n = 0; n < 4; n++)
#pragma unroll
            for (int d = 0; d < 4; d++) vst[a][n][d] = 0.f;

    // combo order: corrections first (acc small -> RZ harmless), main last
    const int AI[6] = {0, 0, 1, 1, 2, 0};
    const int BJ[6] = {1, 2, 0, 1, 0, 0};

#pragma unroll 1
    for (int t = 0; t < T_STEPS; t++) {
        const int img = t * BATCH + bidx;
        __syncthreads();   // protect B smem from previous iteration's reads

        // ---- stage B direct from g_h2s: 3 splits x 2 kh x 64 px x 64 h ----
#pragma unroll
        for (int q8 = 0; q8 < 12; q8++) {
            int f = tid + q8 * 256;      // 0..3071
            int q = f & 7;
            int p = f >> 3;              // 0..383
            int px = p & 63;
            int tt = p >> 6;             // 0..5
            int kh = tt & 1;
            int split = tt >> 1;
            u32 dst = sb + C3_B_OFF + split * C3_B_SPLIT + kh * C3_B_KH
                      + px * BSTR + q * 16;
            const char* src = (const char*)g_h2s +
                (((size_t)split * HSPLIT +
                  (((size_t)img * HW + hw0 + px) * 128 + kh * 64 + q * 8)) << 1);
            cp16(dst, src, true);
        }
        cp_commit();
        cp_wait0();        // also covers A tiles at t==0
        __syncthreads();

        float tot[2][4][4];
#pragma unroll
        for (int a = 0; a < 2; a++)
#pragma unroll
            for (int n = 0; n < 4; n++)
#pragma unroll
                for (int d = 0; d < 4; d++) tot[a][n][d] = 0.f;

        // corrections (combos 0-4) chained, flushed once; then main chained
        float acc[2][4][4];
#pragma unroll
        for (int a = 0; a < 2; a++)
#pragma unroll
            for (int n = 0; n < 4; n++)
#pragma unroll
                for (int d = 0; d < 4; d++) acc[a][n][d] = 0.f;

#pragma unroll 1
        for (int c = 0; c < 6; c++) {
            const int ai = AI[c], bj = BJ[c];
#pragma unroll
            for (int kh = 0; kh < 2; kh++) {
#pragma unroll
                for (int ks = 0; ks < 4; ks++) {
                    u32 afr[2][4];
                    u32 ab = sb + ai * C3_A_SPLIT + kh * C3_A_KH + (u32)(m0 * BSTR)
                             + aLane + ks * 32;
                    ldm4(afr[0], ab);
                    ldm4(afr[1], ab + 16 * BSTR);
                    const u32 bbase = sb + C3_B_OFF + bj * C3_B_SPLIT + kh * C3_B_KH
                                      + (u32)(ks * 32);
#pragma unroll
                    for (int np = 0; np < 2; np++) {
                        u32 b4[4];
                        ldm4(b4, bbase + (u32)((n0 + np * 16) * BSTR) + bLane4);
                        mma16816(acc[0][2 * np],     afr[0], b4);
                        mma16816(acc[1][2 * np],     afr[1], b4);
                        mma16816(acc[0][2 * np + 1], afr[0], b4 + 2);
                        mma16816(acc[1][2 * np + 1], afr[1], b4 + 2);
                    }
                }
            }
            if (c == 4) {   // flush corrections before the main term
#pragma unroll
                for (int a = 0; a < 2; a++)
#pragma unroll
                    for (int n = 0; n < 4; n++)
#pragma unroll
                        for (int d = 0; d < 4; d++) {
                            tot[a][n][d] += acc[a][n][d];
                            acc[a][n][d] = 0.f;
                        }
            }
        }
#pragma unroll
        for (int a = 0; a < 2; a++)
#pragma unroll
            for (int n = 0; n < 4; n++)
#pragma unroll
                for (int d = 0; d < 4; d++) tot[a][n][d] += acc[a][n][d];

        // ---- epilogue: BN + LIF + store spikes ----
#pragma unroll
        for (int nt = 0; nt < 4; nt++) {
            int n = n0 + nt * 8 + 2 * t2;
#pragma unroll
            for (int mt = 0; mt < 2; mt++) {
                int clo = cb * 128 + m0 + mt * 16 + g;
                float s[4];
#pragma unroll
                for (int d = 0; d < 4; d++) {
                    int h = d >> 1;
                    float h3 = tot[mt][nt][d] * scv[mt][h] + biv[mt][h];
                    float v = vst[mt][nt][d];
                    v = v + (h3 - v) * 0.5f;
                    float sp = (v >= 1.0f) ? 1.0f : 0.0f;
                    s[d] = sp;
                    vst[mt][nt][d] = v * (1.0f - sp);
                }
                *(float2*)&out[((size_t)img * COUT + clo) * HW + hw0 + n] =
                    make_float2(s[0], s[1]);
                *(float2*)&out[((size_t)img * COUT + clo + 8) * HW + hw0 + n] =
                    make_float2(s[2], s[3]);
            }
        }
    }
}

// ---------------------------------------------------------------------------
extern "C" void kernel_launch(void* const* d_in, const int* in_sizes, int n_in,
                              void* d_out, int out_size)
{
    const float* x  = (const float*)d_in[0];
    const float* w1 = (const float*)d_in[1];
    const float* g1 = (const float*)d_in[2];
    const float* b1 = (const float*)d_in[3];
    const float* m1 = (const float*)d_in[4];
    const float* v1 = (const float*)d_in[5];
    const float* w2 = (const float*)d_in[6];
    const float* g2 = (const float*)d_in[7];
    const float* b2 = (const float*)d_in[8];
    const float* m2 = (const float*)d_in[9];
    const float* v2 = (const float*)d_in[10];
    const float* w3 = (const float*)d_in[11];
    const float* g3 = (const float*)d_in[12];
    const float* b3 = (const float*)d_in[13];
    const float* m3 = (const float*)d_in[14];
    const float* v3 = (const float*)d_in[15];
    float* out = (float*)d_out;

    cudaFuncSetAttribute(conv1_hmma_kernel,
                         cudaFuncAttributeMaxDynamicSharedMemorySize, SMEM_CONV1);
    cudaFuncSetAttribute(conv2_hmma_kernel,
                         cudaFuncAttributeMaxDynamicSharedMemorySize, SMEM_CONV2);
    cudaFuncSetAttribute(conv3_lif_kernel,
                         cudaFuncAttributeMaxDynamicSharedMemorySize, SMEM_CONV3);

    // weight splits
    prep_w1s_kernel<<<(128 * 256 + 255) / 256, 256>>>(w1);
    prep_w2a_kernel<<<(9 * 128 * 128 + 255) / 256, 256>>>(w2);
    prep_w3s_kernel<<<(256 * 128 + 255) / 256, 256>>>(w3);

    // conv1: 1x1 256->128 + BN1 via HMMA -> bf16x3 channel-last splits
    conv1_hmma_kernel<<<dim3(49, NIMG), 256, SMEM_CONV1>>>(x, g1, b1, m1, v1);

    // conv2: 3x3 128->128 + BN2 via mma.sync -> bf16x3 channel-last g_h2s
    conv2_hmma_kernel<<<dim3(28, NIMG), 256, SMEM_CONV2>>>(g2, b2, m2, v2);

    // conv3 + BN3 + LIF fused -> d_out spikes
    conv3_lif_kernel<<<dim3(49, BATCH, 2), 256, SMEM_CONV3>>>(g3, b3, m3, v3, out);
}